// round 12
// baseline (speedup 1.0000x reference)
#include <cuda_runtime.h>
#include <math.h>
#include <stdint.h>

#define B_   32
#define N_   512
#define C_   768
#define H_   12
#define D_   64
#define HID_ 3072
#define M_   (B_*N_)   // 16384 rows

// ---------------- scratch (device globals; no allocation allowed) ----------
__device__ float g_h1  [(size_t)M_ * C_];
__device__ float g_qkv [(size_t)M_ * 3 * C_];
__device__ float g_attn[(size_t)M_ * C_];
__device__ float g_x2  [(size_t)M_ * C_];
__device__ float g_ln2 [(size_t)M_ * C_];
__device__ float g_fc1 [(size_t)M_ * HID_];
// tf32-rounded weights: qkv_w | proj_w | fc1_w | fc2_w
#define RW_QKV 0
#define RW_PROJ (3*C_*C_)
#define RW_FC1  (RW_PROJ + C_*C_)
#define RW_FC2  (RW_FC1 + HID_*C_)
#define RW_TOT  (RW_FC2 + C_*HID_)
__device__ float g_rw[(size_t)RW_TOT];

// ================= small helpers ===========================================
__device__ __forceinline__ void cp16(uint32_t saddr, const void* g) {
    asm volatile("cp.async.cg.shared.global [%0], [%1], 16;" :: "r"(saddr), "l"(g) : "memory");
}
__device__ __forceinline__ uint32_t smem_u32(const void* p) {
    uint32_t a;
    asm("{ .reg .u64 t; cvta.to.shared.u64 t, %1; cvt.u32.u64 %0, t; }" : "=r"(a) : "l"(p));
    return a;
}
__device__ __forceinline__ uint32_t f2tf32(float f) {
    uint32_t r;
    asm("cvt.rna.tf32.f32 %0, %1;" : "=r"(r) : "f"(f));
    return r;
}
__device__ __forceinline__ float tf32r(float f) { return __uint_as_float(f2tf32(f)); }
__device__ __forceinline__ void split2(float v, uint32_t& hi, uint32_t& lo) {
    hi = f2tf32(v);
    lo = f2tf32(v - __uint_as_float(hi));
}
__device__ __forceinline__ void mma_tf32(float* c, const uint32_t* a, const uint32_t* b) {
    asm volatile("mma.sync.aligned.m16n8k8.row.col.f32.tf32.tf32.f32 "
                 "{%0,%1,%2,%3}, {%4,%5,%6,%7}, {%8,%9}, {%0,%1,%2,%3};"
                 : "+f"(c[0]), "+f"(c[1]), "+f"(c[2]), "+f"(c[3])
                 : "r"(a[0]), "r"(a[1]), "r"(a[2]), "r"(a[3]), "r"(b[0]), "r"(b[1]));
}
__device__ __forceinline__ void ldsm_x4(uint32_t* r, uint32_t addr) {
    asm volatile("ldmatrix.sync.aligned.m8n8.x4.shared.b16 {%0,%1,%2,%3}, [%4];"
                 : "=r"(r[0]), "=r"(r[1]), "=r"(r[2]), "=r"(r[3]) : "r"(addr));
}

// ================= weight tf32 pre-round (single kernel) ===================
__global__ void __launch_bounds__(256) round_all_kernel(const float* __restrict__ w0,
                                                        const float* __restrict__ w1,
                                                        const float* __restrict__ w2,
                                                        const float* __restrict__ w3,
                                                        float* __restrict__ out)
{
    const size_t i = ((size_t)blockIdx.x * 256 + threadIdx.x) * 4;
    if (i >= (size_t)RW_TOT) return;
    const float* src;
    size_t off;
    if (i < (size_t)RW_PROJ)      { src = w0; off = i; }
    else if (i < (size_t)RW_FC1)  { src = w1; off = i - RW_PROJ; }
    else if (i < (size_t)RW_FC2)  { src = w2; off = i - RW_FC1; }
    else                          { src = w3; off = i - RW_FC2; }
    float4 v = *(const float4*)(src + off);
    v.x = tf32r(v.x); v.y = tf32r(v.y); v.z = tf32r(v.z); v.w = tf32r(v.w);
    *(float4*)(out + i) = v;
}

// ================= tf32 mma.sync GEMM ======================================
// CTA 128x128, 4 warps, warp tile 64x64 (mma:ldsm = 4:1). 3-stage cp.async.
#define BKK 32
#define PAD 36
#define AS_BYTES (128 * PAD * 4)
#define STAGE_B  (2 * AS_BYTES)
#define GSMEM    (3 * STAGE_B)

template <int MODE>
__global__ void __launch_bounds__(128, 2) tc_gemm(const float* __restrict__ A,
                                                  const float* __restrict__ W,
                                                  const float* __restrict__ bias,
                                                  const float* __restrict__ res,
                                                  float* __restrict__ Cout,
                                                  int M, int Nn, int K)
{
    extern __shared__ float smem[];
    const uint32_t sbase = smem_u32(smem);
    const int tid = threadIdx.x;
    const int bm = blockIdx.y, bn = blockIdx.x;

    const float* Ab = A + (size_t)bm * 128 * K;
    const float* Wb = W + (size_t)bn * 128 * K;
    const int nk = K / BKK;

    auto load_stage = [&](int slot, int k0) {
        const uint32_t sA = sbase + slot * STAGE_B;
        const uint32_t sB = sA + AS_BYTES;
        #pragma unroll
        for (int t = 0; t < 8; t++) {
            const int c = tid + 128 * t;       // 0..1023
            const int row = c >> 3;
            const int seg = c & 7;
            const uint32_t off = (uint32_t)(row * PAD + seg * 4) * 4u;
            cp16(sA + off, Ab + (size_t)row * K + k0 + seg * 4);
            cp16(sB + off, Wb + (size_t)row * K + k0 + seg * 4);
        }
        asm volatile("cp.async.commit_group;" ::: "memory");
    };

    load_stage(0, 0);
    load_stage(1, BKK);

    const int wid = tid >> 5, lane = tid & 31;
    const int wm = (wid >> 1) * 64;
    const int wn = (wid & 1) * 64;
    const int qr = lane >> 2, qc = lane & 3;

    const int l7 = lane & 7;
    const uint32_t aOff = (uint32_t)((wm + l7 + ((lane >> 3) & 1) * 8) * PAD
                                     + ((lane >> 4) & 1) * 4) * 4u;
    const uint32_t bOff4 = (uint32_t)((wn + l7 + ((lane >> 4) & 1) * 8) * PAD
                                      + ((lane >> 3) & 1) * 4) * 4u;

    float acc[4][8][4];
    #pragma unroll
    for (int mi = 0; mi < 4; mi++)
        #pragma unroll
        for (int ni = 0; ni < 8; ni++)
            #pragma unroll
            for (int u = 0; u < 4; u++) acc[mi][ni][u] = 0.0f;

    int slot = 0, slot2 = 2;
    for (int i = 0; i < nk; i++) {
        if (i == nk - 1) asm volatile("cp.async.wait_group 0;" ::: "memory");
        else             asm volatile("cp.async.wait_group 1;" ::: "memory");
        __syncthreads();
        if (i + 2 < nk) load_stage(slot2, (i + 2) * BKK);

        const uint32_t sA = sbase + slot * STAGE_B;
        const uint32_t sB = sA + AS_BYTES;
        #pragma unroll
        for (int kc = 0; kc < 4; kc++) {
            uint32_t af[4][4], bf[4][4];
            #pragma unroll
            for (int mi = 0; mi < 4; mi++)
                ldsm_x4(af[mi], sA + aOff + (uint32_t)(mi * 16 * PAD * 4) + (uint32_t)(kc * 32));
            #pragma unroll
            for (int np = 0; np < 4; np++)
                ldsm_x4(bf[np], sB + bOff4 + (uint32_t)(np * 16 * PAD * 4) + (uint32_t)(kc * 32));
            #pragma unroll
            for (int mi = 0; mi < 4; mi++)
                #pragma unroll
                for (int ni = 0; ni < 8; ni++)
                    mma_tf32(acc[mi][ni], af[mi], &bf[ni >> 1][(ni & 1) * 2]);
        }
        slot = (slot + 1 == 3) ? 0 : slot + 1;
        slot2 = (slot2 + 1 == 3) ? 0 : slot2 + 1;
    }

    #pragma unroll
    for (int mi = 0; mi < 4; mi++) {
        #pragma unroll
        for (int ni = 0; ni < 8; ni++) {
            const int col = bn * 128 + wn + ni * 8 + 2 * qc;
            #pragma unroll
            for (int half = 0; half < 2; half++) {
                const size_t row = (size_t)bm * 128 + wm + mi * 16 + qr + half * 8;
                float v0 = acc[mi][ni][half * 2 + 0];
                float v1 = acc[mi][ni][half * 2 + 1];
                if (MODE == 1) {
                    v0 = 2.0f * (v0 + bias[col]);
                    v1 = 2.0f * (v1 + bias[col + 1]);
                } else if (MODE == 2) {
                    v0 += bias[col];
                    v1 += bias[col + 1];
                    v0 = 0.5f * v0 * (1.0f + erff(v0 * 0.70710678118654752f));
                    v1 = 0.5f * v1 * (1.0f + erff(v1 * 0.70710678118654752f));
                    v0 = tf32r(v0);
                    v1 = tf32r(v1);
                } else if (MODE == 3) {
                    const float* rr = res + row * Nn + col;
                    v0 += bias[col] + rr[0];
                    v1 += bias[col + 1] + rr[1];
                }
                *(float2*)(Cout + row * Nn + col) = make_float2(v0, v1);
            }
        }
    }
}

// ---------------- fused LayerNorm (tf32-rounded output) --------------------
__global__ void __launch_bounds__(256) ln_kernel(const float* __restrict__ x,
                                                 const float* __restrict__ w,
                                                 const float* __restrict__ b,
                                                 float* __restrict__ out)
{
    __shared__ float red[8];
    const int row = blockIdx.x;
    const int t   = threadIdx.x;
    const float* xr = x + (size_t)row * C_;

    float v0 = xr[t], v1 = xr[t + 256], v2 = xr[t + 512];
    float s = v0 + v1 + v2;
    #pragma unroll
    for (int o = 16; o; o >>= 1) s += __shfl_xor_sync(0xffffffffu, s, o);
    if ((t & 31) == 0) red[t >> 5] = s;
    __syncthreads();
    float tot = red[0]+red[1]+red[2]+red[3]+red[4]+red[5]+red[6]+red[7];
    const float mu = tot * (1.0f / C_);

    float d0 = v0 - mu, d1 = v1 - mu, d2 = v2 - mu;
    float q = d0*d0 + d1*d1 + d2*d2;
    #pragma unroll
    for (int o = 16; o; o >>= 1) q += __shfl_xor_sync(0xffffffffu, q, o);
    __syncthreads();
    if ((t & 31) == 0) red[t >> 5] = q;
    __syncthreads();
    float var = (red[0]+red[1]+red[2]+red[3]+red[4]+red[5]+red[6]+red[7]) * (1.0f / C_);
    const float rstd = rsqrtf(var + 1e-5f);

    float* orow = out + (size_t)row * C_;
    orow[t]       = tf32r(d0 * rstd * w[t]       + b[t]);
    orow[t + 256] = tf32r(d1 * rstd * w[t + 256] + b[t + 256]);
    orow[t + 512] = tf32r(d2 * rstd * w[t + 512] + b[t + 512]);
}

// ================= flash attention v6: hoisted Q split =====================
// S = (Qh+Ql)*Kh, O += (Ph+Pl)*Vh. Q split once into smem; K/V hi-only.
#define AP 68
#define OQH 0
#define OQL (128*AP)                // 8704
#define OKH (2*128*AP)              // 17408
#define OVH (OKH + 64*AP)
#define ATT_SMEM ((OKH + 2*64*AP) * 4)   // 104448 B

__global__ void __launch_bounds__(256, 2) attn_mma(const float* __restrict__ qkv,
                                                   float* __restrict__ out)
{
    extern __shared__ float sm[];
    const uint32_t sbase = smem_u32(sm);
    float* Qh = sm + OQH;
    float* Ql = sm + OQL;
    float* Kh = sm + OKH;
    float* Vth = sm + OVH;

    const int qt = blockIdx.x;
    const int bh = blockIdx.y;
    const int h  = bh % H_;
    const int b  = bh / H_;
    const int tid = threadIdx.x;
    const int w = tid >> 5, lane = tid & 31;
    const int qr = lane >> 2, qc = lane & 3;
    const int mrow = w * 16;
    const size_t rowbase = (size_t)b * N_ + (size_t)qt * 128;

    const int l7 = lane & 7;
    const uint32_t aOff = (uint32_t)((mrow + l7 + ((lane >> 3) & 1) * 8) * AP
                                     + ((lane >> 4) & 1) * 4) * 4u;
    const uint32_t bOff4 = (uint32_t)((l7 + ((lane >> 4) & 1) * 8) * AP
                                      + ((lane >> 3) & 1) * 4) * 4u;
    const int src0 = (lane & ~3) | (qc >> 1);
    const int src1 = src0 + 2;

    // ---- stage + split Q once (128 x 64) ----
    #pragma unroll
    for (int t = 0; t < 8; t++) {
        int i = tid + t * 256;
        int row = i >> 4, c4 = (i & 15) * 4;
        float4 v = *(const float4*)(qkv + (rowbase + row) * (3 * C_) + h * D_ + c4);
        uint32_t h0,l0,h1,l1,h2,l2,h3,l3;
        split2(v.x, h0, l0); split2(v.y, h1, l1); split2(v.z, h2, l2); split2(v.w, h3, l3);
        *(uint4*)(Qh + row * AP + c4) = make_uint4(h0, h1, h2, h3);
        *(uint4*)(Ql + row * AP + c4) = make_uint4(l0, l1, l2, l3);
    }

    float m0 = -INFINITY, m1 = -INFINITY, l0s = 0.0f, l1s = 0.0f;
    float O[8][4];
    #pragma unroll
    for (int nt = 0; nt < 8; nt++)
        #pragma unroll
        for (int u = 0; u < 4; u++) O[nt][u] = 0.0f;

    for (int kt = 0; kt < 8; kt++) {
        __syncthreads();   // covers Q writes (kt==0) and prior tile reads
        // ---- load K (hi only) and V transposed (hi only) ----
        #pragma unroll
        for (int t = 0; t < 4; t++) {
            int i = tid + t * 256;
            int row = i >> 4, c4 = (i & 15) * 4;
            const float* src = qkv + ((size_t)b * N_ + kt * 64 + row) * (3 * C_) + C_ + h * D_ + c4;
            float4 kv = *(const float4*)src;
            float4 vv = *(const float4*)(src + C_);
            *(uint4*)(Kh + row * AP + c4) =
                make_uint4(f2tf32(kv.x), f2tf32(kv.y), f2tf32(kv.z), f2tf32(kv.w));
            ((uint32_t*)Vth)[(c4 + 0) * AP + row] = f2tf32(vv.x);
            ((uint32_t*)Vth)[(c4 + 1) * AP + row] = f2tf32(vv.y);
            ((uint32_t*)Vth)[(c4 + 2) * AP + row] = f2tf32(vv.z);
            ((uint32_t*)Vth)[(c4 + 3) * AP + row] = f2tf32(vv.w);
        }
        __syncthreads();

        // ---- S = (Qh+Ql) Kh^T ----
        float S[8][4];
        #pragma unroll
        for (int nt = 0; nt < 8; nt++)
            #pragma unroll
            for (int u = 0; u < 4; u++) S[nt][u] = 0.0f;

        #pragma unroll
        for (int kk = 0; kk < 8; kk++) {
            uint32_t ah[4], al[4];
            ldsm_x4(ah, sbase + aOff + (uint32_t)(kk * 32));
            ldsm_x4(al, sbase + (uint32_t)(OQL * 4) + aOff + (uint32_t)(kk * 32));
            #pragma unroll
            for (int np = 0; np < 4; np++) {
                uint32_t kh4[4];
                ldsm_x4(kh4, sbase + (uint32_t)(OKH * 4) + bOff4 + (uint32_t)(np * 16 * AP * 4 + kk * 32));
                mma_tf32(S[2*np],   ah, kh4);
                mma_tf32(S[2*np],   al, kh4);
                mma_tf32(S[2*np+1], ah, kh4 + 2);
                mma_tf32(S[2*np+1], al, kh4 + 2);
            }
        }

        // ---- online softmax ----
        float mt0 = -INFINITY, mt1 = -INFINITY;
        #pragma unroll
        for (int nt = 0; nt < 8; nt++) {
            #pragma unroll
            for (int u = 0; u < 4; u++) S[nt][u] *= 0.125f;
            mt0 = fmaxf(mt0, fmaxf(S[nt][0], S[nt][1]));
            mt1 = fmaxf(mt1, fmaxf(S[nt][2], S[nt][3]));
        }
        mt0 = fmaxf(mt0, __shfl_xor_sync(0xffffffffu, mt0, 1));
        mt0 = fmaxf(mt0, __shfl_xor_sync(0xffffffffu, mt0, 2));
        mt1 = fmaxf(mt1, __shfl_xor_sync(0xffffffffu, mt1, 1));
        mt1 = fmaxf(mt1, __shfl_xor_sync(0xffffffffu, mt1, 2));
        const float mn0 = fmaxf(m0, mt0), mn1 = fmaxf(m1, mt1);
        const float a0 = __expf(m0 - mn0), a1 = __expf(m1 - mn1);
        float ls0 = 0.0f, ls1 = 0.0f;
        #pragma unroll
        for (int nt = 0; nt < 8; nt++) {
            S[nt][0] = __expf(S[nt][0] - mn0);
            S[nt][1] = __expf(S[nt][1] - mn0);
            S[nt][2] = __expf(S[nt][2] - mn1);
            S[nt][3] = __expf(S[nt][3] - mn1);
            ls0 += S[nt][0] + S[nt][1];
            ls1 += S[nt][2] + S[nt][3];
        }
        ls0 += __shfl_xor_sync(0xffffffffu, ls0, 1);
        ls0 += __shfl_xor_sync(0xffffffffu, ls0, 2);
        ls1 += __shfl_xor_sync(0xffffffffu, ls1, 1);
        ls1 += __shfl_xor_sync(0xffffffffu, ls1, 2);
        l0s = l0s * a0 + ls0;
        l1s = l1s * a1 + ls1;
        m0 = mn0; m1 = mn1;
        #pragma unroll
        for (int nt = 0; nt < 8; nt++) {
            O[nt][0] *= a0; O[nt][1] *= a0;
            O[nt][2] *= a1; O[nt][3] *= a1;
        }

        // ---- O += (Ph+Pl) Vh: P fragments via quad shuffles of S[kk] ----
        #pragma unroll
        for (int kk = 0; kk < 8; kk++) {
            const float v00 = __shfl_sync(0xffffffffu, S[kk][0], src0);
            const float v01 = __shfl_sync(0xffffffffu, S[kk][1], src0);
            const float v10 = __shfl_sync(0xffffffffu, S[kk][2], src0);
            const float v11 = __shfl_sync(0xffffffffu, S[kk][3], src0);
            const float w00 = __shfl_sync(0xffffffffu, S[kk][0], src1);
            const float w01 = __shfl_sync(0xffffffffu, S[kk][1], src1);
            const float w10 = __shfl_sync(0xffffffffu, S[kk][2], src1);
            const float w11 = __shfl_sync(0xffffffffu, S[kk][3], src1);
            const float a0f = (qc & 1) ? v01 : v00;
            const float a1f = (qc & 1) ? v11 : v10;
            const float a2f = (qc & 1) ? w01 : w00;
            const float a3f = (qc & 1) ? w11 : w10;
            uint32_t ph[4], pl[4];
            split2(a0f, ph[0], pl[0]);
            split2(a1f, ph[1], pl[1]);
            split2(a2f, ph[2], pl[2]);
            split2(a3f, ph[3], pl[3]);
            #pragma unroll
            for (int np = 0; np < 4; np++) {
                uint32_t vh4[4];
                ldsm_x4(vh4, sbase + (uint32_t)(OVH * 4) + bOff4 + (uint32_t)(np * 16 * AP * 4 + kk * 32));
                mma_tf32(O[2*np],   ph, vh4);
                mma_tf32(O[2*np],   pl, vh4);
                mma_tf32(O[2*np+1], ph, vh4 + 2);
                mma_tf32(O[2*np+1], pl, vh4 + 2);
            }
        }
    }

    const float inv0 = 1.0f / l0s, inv1 = 1.0f / l1s;
    #pragma unroll
    for (int nt = 0; nt < 8; nt++) {
        const int col = h * D_ + nt * 8 + 2 * qc;
        const size_t r0 = rowbase + mrow + qr;
        *(float2*)(out + r0 * C_ + col) =
            make_float2(tf32r(O[nt][0] * inv0), tf32r(O[nt][1] * inv0));
        *(float2*)(out + (r0 + 8) * C_ + col) =
            make_float2(tf32r(O[nt][2] * inv1), tf32r(O[nt][3] * inv1));
    }
}

// ---------------- host launcher -------------------------------------------
extern "C" void kernel_launch(void* const* d_in, const int* in_sizes, int n_in,
                              void* d_out, int out_size)
{
    (void)in_sizes; (void)n_in; (void)out_size;
    const float* x      = (const float*)d_in[0];
    const float* ln1_w  = (const float*)d_in[1];
    const float* ln1_b  = (const float*)d_in[2];
    const float* qkv_w  = (const float*)d_in[3];
    const float* proj_w = (const float*)d_in[4];
    const float* proj_b = (const float*)d_in[5];
    const float* ln2_w  = (const float*)d_in[6];
    const float* ln2_b  = (const float*)d_in[7];
    const float* fc1_w  = (const float*)d_in[8];
    const float* fc1_b  = (const float*)d_in[9];
    const float* fc2_w  = (const float*)d_in[10];
    const float* fc2_b  = (const float*)d_in[11];
    float* out = (float*)d_out;

    float *h1, *qkvb, *attn, *x2, *ln2o, *fc1o, *rw;
    cudaGetSymbolAddress((void**)&h1,   g_h1);
    cudaGetSymbolAddress((void**)&qkvb, g_qkv);
    cudaGetSymbolAddress((void**)&attn, g_attn);
    cudaGetSymbolAddress((void**)&x2,   g_x2);
    cudaGetSymbolAddress((void**)&ln2o, g_ln2);
    cudaGetSymbolAddress((void**)&fc1o, g_fc1);
    cudaGetSymbolAddress((void**)&rw,   g_rw);

    static bool attr_done = false;
    if (!attr_done) {
        cudaFuncSetAttribute(tc_gemm<0>, cudaFuncAttributeMaxDynamicSharedMemorySize, GSMEM);
        cudaFuncSetAttribute(tc_gemm<1>, cudaFuncAttributeMaxDynamicSharedMemorySize, GSMEM);
        cudaFuncSetAttribute(tc_gemm<2>, cudaFuncAttributeMaxDynamicSharedMemorySize, GSMEM);
        cudaFuncSetAttribute(tc_gemm<3>, cudaFuncAttributeMaxDynamicSharedMemorySize, GSMEM);
        cudaFuncSetAttribute(attn_mma,   cudaFuncAttributeMaxDynamicSharedMemorySize, ATT_SMEM);
        attr_done = true;
    }

    round_all_kernel<<<(RW_TOT/4 + 255)/256, 256>>>(qkv_w, proj_w, fc1_w, fc2_w, rw);

    ln_kernel<<<M_, 256>>>(x, ln1_w, ln1_b, h1);
    tc_gemm<0><<<dim3(3*C_/128, M_/128), 128, GSMEM>>>(h1, rw + RW_QKV, nullptr, nullptr, qkvb, M_, 3*C_, C_);
    attn_mma<<<dim3(4, B_*H_), 256, ATT_SMEM>>>(qkvb, attn);
    tc_gemm<1><<<dim3(C_/128, M_/128), 128, GSMEM>>>(attn, rw + RW_PROJ, proj_b, nullptr, x2, M_, C_, C_);
    ln_kernel<<<M_, 256>>>(x2, ln2_w, ln2_b, ln2o);
    tc_gemm<2><<<dim3(HID_/128, M_/128), 128, GSMEM>>>(ln2o, rw + RW_FC1, fc1_b, nullptr, fc1o, M_, HID_, C_);
    tc_gemm<3><<<dim3(C_/128, M_/128), 128, GSMEM>>>(fc1o, rw + RW_FC2, fc2_b, x2, out, M_, C_, HID_);
}

// round 13
// speedup vs baseline: 1.5234x; 1.5234x over previous
#include <cuda_runtime.h>
#include <math.h>
#include <stdint.h>

#define B_   32
#define N_   512
#define C_   768
#define H_   12
#define D_   64
#define HID_ 3072
#define M_   (B_*N_)   // 16384 rows

// ---------------- scratch (device globals; no allocation allowed) ----------
__device__ float g_h1  [(size_t)M_ * C_];
__device__ float g_qkv [(size_t)M_ * 3 * C_];
__device__ float g_attn[(size_t)M_ * C_];
__device__ float g_x2  [(size_t)M_ * C_];
__device__ float g_ln2 [(size_t)M_ * C_];
__device__ float g_fc1 [(size_t)M_ * HID_];
// tf32-rounded weights: qkv_w | proj_w | fc1_w | fc2_w
#define RW_QKV 0
#define RW_PROJ (3*C_*C_)
#define RW_FC1  (RW_PROJ + C_*C_)
#define RW_FC2  (RW_FC1 + HID_*C_)
#define RW_TOT  (RW_FC2 + C_*HID_)
__device__ float g_rw[(size_t)RW_TOT];

// ================= small helpers ===========================================
__device__ __forceinline__ void cp16(uint32_t saddr, const void* g) {
    asm volatile("cp.async.cg.shared.global [%0], [%1], 16;" :: "r"(saddr), "l"(g) : "memory");
}
__device__ __forceinline__ uint32_t smem_u32(const void* p) {
    uint32_t a;
    asm("{ .reg .u64 t; cvta.to.shared.u64 t, %1; cvt.u32.u64 %0, t; }" : "=r"(a) : "l"(p));
    return a;
}
__device__ __forceinline__ uint32_t f2tf32(float f) {
    uint32_t r;
    asm("cvt.rna.tf32.f32 %0, %1;" : "=r"(r) : "f"(f));
    return r;
}
__device__ __forceinline__ float tf32r(float f) { return __uint_as_float(f2tf32(f)); }
__device__ __forceinline__ void split2(float v, uint32_t& hi, uint32_t& lo) {
    hi = f2tf32(v);
    lo = f2tf32(v - __uint_as_float(hi));
}
__device__ __forceinline__ void mma_tf32(float* c, const uint32_t* a, const uint32_t* b) {
    asm volatile("mma.sync.aligned.m16n8k8.row.col.f32.tf32.tf32.f32 "
                 "{%0,%1,%2,%3}, {%4,%5,%6,%7}, {%8,%9}, {%0,%1,%2,%3};"
                 : "+f"(c[0]), "+f"(c[1]), "+f"(c[2]), "+f"(c[3])
                 : "r"(a[0]), "r"(a[1]), "r"(a[2]), "r"(a[3]), "r"(b[0]), "r"(b[1]));
}
__device__ __forceinline__ void ldsm_x4(uint32_t* r, uint32_t addr) {
    asm volatile("ldmatrix.sync.aligned.m8n8.x4.shared.b16 {%0,%1,%2,%3}, [%4];"
                 : "=r"(r[0]), "=r"(r[1]), "=r"(r[2]), "=r"(r[3]) : "r"(addr));
}

// ================= weight tf32 pre-round (single kernel) ===================
__global__ void __launch_bounds__(256) round_all_kernel(const float* __restrict__ w0,
                                                        const float* __restrict__ w1,
                                                        const float* __restrict__ w2,
                                                        const float* __restrict__ w3,
                                                        float* __restrict__ out)
{
    const size_t i = ((size_t)blockIdx.x * 256 + threadIdx.x) * 4;
    if (i >= (size_t)RW_TOT) return;
    const float* src;
    size_t off;
    if (i < (size_t)RW_PROJ)      { src = w0; off = i; }
    else if (i < (size_t)RW_FC1)  { src = w1; off = i - RW_PROJ; }
    else if (i < (size_t)RW_FC2)  { src = w2; off = i - RW_FC1; }
    else                          { src = w3; off = i - RW_FC2; }
    float4 v = *(const float4*)(src + off);
    v.x = tf32r(v.x); v.y = tf32r(v.y); v.z = tf32r(v.z); v.w = tf32r(v.w);
    *(float4*)(out + i) = v;
}

// ================= tf32 mma.sync GEMM ======================================
// CTA 128x128, 4 warps, warp tile 64x64 (mma:ldsm = 4:1). 3-stage cp.async.
// NO min-blocks reg cap: ptxas free to use ~190 regs; 2 CTAs/SM still fit
// (2*128*192 = 49K regs < 64K, 2*110.6KB smem < 228KB).
#define BKK 32
#define PAD 36
#define AS_BYTES (128 * PAD * 4)
#define STAGE_B  (2 * AS_BYTES)
#define GSMEM    (3 * STAGE_B)

template <int MODE>
__global__ void __launch_bounds__(128) tc_gemm(const float* __restrict__ A,
                                               const float* __restrict__ W,
                                               const float* __restrict__ bias,
                                               const float* __restrict__ res,
                                               float* __restrict__ Cout,
                                               int M, int Nn, int K)
{
    extern __shared__ float smem[];
    const uint32_t sbase = smem_u32(smem);
    const int tid = threadIdx.x;
    const int bm = blockIdx.y, bn = blockIdx.x;

    const float* Ab = A + (size_t)bm * 128 * K;
    const float* Wb = W + (size_t)bn * 128 * K;
    const int nk = K / BKK;

    auto load_stage = [&](int slot, int k0) {
        const uint32_t sA = sbase + slot * STAGE_B;
        const uint32_t sB = sA + AS_BYTES;
        #pragma unroll
        for (int t = 0; t < 8; t++) {
            const int c = tid + 128 * t;       // 0..1023
            const int row = c >> 3;
            const int seg = c & 7;
            const uint32_t off = (uint32_t)(row * PAD + seg * 4) * 4u;
            cp16(sA + off, Ab + (size_t)row * K + k0 + seg * 4);
            cp16(sB + off, Wb + (size_t)row * K + k0 + seg * 4);
        }
        asm volatile("cp.async.commit_group;" ::: "memory");
    };

    load_stage(0, 0);
    load_stage(1, BKK);

    const int wid = tid >> 5, lane = tid & 31;
    const int wm = (wid >> 1) * 64;
    const int wn = (wid & 1) * 64;
    const int qr = lane >> 2, qc = lane & 3;

    const int l7 = lane & 7;
    const uint32_t aOff = (uint32_t)((wm + l7 + ((lane >> 3) & 1) * 8) * PAD
                                     + ((lane >> 4) & 1) * 4) * 4u;
    const uint32_t bOff4 = (uint32_t)((wn + l7 + ((lane >> 4) & 1) * 8) * PAD
                                      + ((lane >> 3) & 1) * 4) * 4u;

    float acc[4][8][4];
    #pragma unroll
    for (int mi = 0; mi < 4; mi++)
        #pragma unroll
        for (int ni = 0; ni < 8; ni++)
            #pragma unroll
            for (int u = 0; u < 4; u++) acc[mi][ni][u] = 0.0f;

    int slot = 0, slot2 = 2;
    for (int i = 0; i < nk; i++) {
        if (i == nk - 1) asm volatile("cp.async.wait_group 0;" ::: "memory");
        else             asm volatile("cp.async.wait_group 1;" ::: "memory");
        __syncthreads();
        if (i + 2 < nk) load_stage(slot2, (i + 2) * BKK);

        const uint32_t sA = sbase + slot * STAGE_B;
        const uint32_t sB = sA + AS_BYTES;
        #pragma unroll
        for (int kc = 0; kc < 4; kc++) {
            uint32_t af[4][4], bf[4][4];
            #pragma unroll
            for (int mi = 0; mi < 4; mi++)
                ldsm_x4(af[mi], sA + aOff + (uint32_t)(mi * 16 * PAD * 4) + (uint32_t)(kc * 32));
            #pragma unroll
            for (int np = 0; np < 4; np++)
                ldsm_x4(bf[np], sB + bOff4 + (uint32_t)(np * 16 * PAD * 4) + (uint32_t)(kc * 32));
            #pragma unroll
            for (int mi = 0; mi < 4; mi++)
                #pragma unroll
                for (int ni = 0; ni < 8; ni++)
                    mma_tf32(acc[mi][ni], af[mi], &bf[ni >> 1][(ni & 1) * 2]);
        }
        slot = (slot + 1 == 3) ? 0 : slot + 1;
        slot2 = (slot2 + 1 == 3) ? 0 : slot2 + 1;
    }

    #pragma unroll
    for (int mi = 0; mi < 4; mi++) {
        #pragma unroll
        for (int ni = 0; ni < 8; ni++) {
            const int col = bn * 128 + wn + ni * 8 + 2 * qc;
            #pragma unroll
            for (int half = 0; half < 2; half++) {
                const size_t row = (size_t)bm * 128 + wm + mi * 16 + qr + half * 8;
                float v0 = acc[mi][ni][half * 2 + 0];
                float v1 = acc[mi][ni][half * 2 + 1];
                if (MODE == 1) {
                    v0 = 2.0f * (v0 + bias[col]);
                    v1 = 2.0f * (v1 + bias[col + 1]);
                } else if (MODE == 2) {
                    v0 += bias[col];
                    v1 += bias[col + 1];
                    v0 = 0.5f * v0 * (1.0f + erff(v0 * 0.70710678118654752f));
                    v1 = 0.5f * v1 * (1.0f + erff(v1 * 0.70710678118654752f));
                    v0 = tf32r(v0);
                    v1 = tf32r(v1);
                } else if (MODE == 3) {
                    const float* rr = res + row * Nn + col;
                    v0 += bias[col] + rr[0];
                    v1 += bias[col + 1] + rr[1];
                }
                *(float2*)(Cout + row * Nn + col) = make_float2(v0, v1);
            }
        }
    }
}

// ---------------- fused LayerNorm (tf32-rounded output) --------------------
__global__ void __launch_bounds__(256) ln_kernel(const float* __restrict__ x,
                                                 const float* __restrict__ w,
                                                 const float* __restrict__ b,
                                                 float* __restrict__ out)
{
    __shared__ float red[8];
    const int row = blockIdx.x;
    const int t   = threadIdx.x;
    const float* xr = x + (size_t)row * C_;

    float v0 = xr[t], v1 = xr[t + 256], v2 = xr[t + 512];
    float s = v0 + v1 + v2;
    #pragma unroll
    for (int o = 16; o; o >>= 1) s += __shfl_xor_sync(0xffffffffu, s, o);
    if ((t & 31) == 0) red[t >> 5] = s;
    __syncthreads();
    float tot = red[0]+red[1]+red[2]+red[3]+red[4]+red[5]+red[6]+red[7];
    const float mu = tot * (1.0f / C_);

    float d0 = v0 - mu, d1 = v1 - mu, d2 = v2 - mu;
    float q = d0*d0 + d1*d1 + d2*d2;
    #pragma unroll
    for (int o = 16; o; o >>= 1) q += __shfl_xor_sync(0xffffffffu, q, o);
    __syncthreads();
    if ((t & 31) == 0) red[t >> 5] = q;
    __syncthreads();
    float var = (red[0]+red[1]+red[2]+red[3]+red[4]+red[5]+red[6]+red[7]) * (1.0f / C_);
    const float rstd = rsqrtf(var + 1e-5f);

    float* orow = out + (size_t)row * C_;
    orow[t]       = tf32r(d0 * rstd * w[t]       + b[t]);
    orow[t + 256] = tf32r(d1 * rstd * w[t + 256] + b[t + 256]);
    orow[t + 512] = tf32r(d2 * rstd * w[t + 512] + b[t + 512]);
}

// ================= flash attention v5 (R11, known-good 324us) ==============
// S = (Qh+Ql)*Kh,  O += (Ph+Pl)*Vh.  K/V stored hi-only (tf32-rounded).
#define AP 68
#define OQ  0
#define OKH (128*AP)                // 8704
#define OVH (OKH + 64*AP)           // 13056
#define ATT_SMEM ((OKH + 2*64*AP) * 4)   // 69632 B

__global__ void __launch_bounds__(256, 2) attn_mma(const float* __restrict__ qkv,
                                                   float* __restrict__ out)
{
    extern __shared__ float sm[];
    const uint32_t sbase = smem_u32(sm);
    float* Qs = sm + OQ;
    float* Kh = sm + OKH;
    float* Vth = sm + OVH;

    const int qt = blockIdx.x;
    const int bh = blockIdx.y;
    const int h  = bh % H_;
    const int b  = bh / H_;
    const int tid = threadIdx.x;
    const int w = tid >> 5, lane = tid & 31;
    const int qr = lane >> 2, qc = lane & 3;
    const int mrow = w * 16;
    const size_t rowbase = (size_t)b * N_ + (size_t)qt * 128;

    const int l7 = lane & 7;
    const uint32_t aOff = (uint32_t)((mrow + l7 + ((lane >> 3) & 1) * 8) * AP
                                     + ((lane >> 4) & 1) * 4) * 4u;
    const uint32_t bOff4 = (uint32_t)((l7 + ((lane >> 4) & 1) * 8) * AP
                                      + ((lane >> 3) & 1) * 4) * 4u;
    const int src0 = (lane & ~3) | (qc >> 1);
    const int src1 = src0 + 2;

    // ---- stage Q (128 x 64, fp32) ----
    #pragma unroll
    for (int t = 0; t < 8; t++) {
        int i = tid + t * 256;
        int row = i >> 4, c4 = (i & 15) * 4;
        float4 v = *(const float4*)(qkv + (rowbase + row) * (3 * C_) + h * D_ + c4);
        *(float4*)(Qs + row * AP + c4) = v;
    }

    float m0 = -INFINITY, m1 = -INFINITY, l0s = 0.0f, l1s = 0.0f;
    float O[8][4];
    #pragma unroll
    for (int nt = 0; nt < 8; nt++)
        #pragma unroll
        for (int u = 0; u < 4; u++) O[nt][u] = 0.0f;

    for (int kt = 0; kt < 8; kt++) {
        __syncthreads();
        // ---- load K (hi only) and V transposed (hi only) ----
        #pragma unroll
        for (int t = 0; t < 4; t++) {
            int i = tid + t * 256;
            int row = i >> 4, c4 = (i & 15) * 4;
            const float* src = qkv + ((size_t)b * N_ + kt * 64 + row) * (3 * C_) + C_ + h * D_ + c4;
            float4 kv = *(const float4*)src;
            float4 vv = *(const float4*)(src + C_);
            *(uint4*)(Kh + row * AP + c4) =
                make_uint4(f2tf32(kv.x), f2tf32(kv.y), f2tf32(kv.z), f2tf32(kv.w));
            ((uint32_t*)Vth)[(c4 + 0) * AP + row] = f2tf32(vv.x);
            ((uint32_t*)Vth)[(c4 + 1) * AP + row] = f2tf32(vv.y);
            ((uint32_t*)Vth)[(c4 + 2) * AP + row] = f2tf32(vv.z);
            ((uint32_t*)Vth)[(c4 + 3) * AP + row] = f2tf32(vv.w);
        }
        __syncthreads();

        // ---- S = (Qh+Ql) Kh^T ----
        float S[8][4];
        #pragma unroll
        for (int nt = 0; nt < 8; nt++)
            #pragma unroll
            for (int u = 0; u < 4; u++) S[nt][u] = 0.0f;

        #pragma unroll
        for (int kk = 0; kk < 8; kk++) {
            uint32_t aq[4], ah[4], al[4];
            ldsm_x4(aq, sbase + aOff + (uint32_t)(kk * 32));
            #pragma unroll
            for (int u = 0; u < 4; u++) split2(__uint_as_float(aq[u]), ah[u], al[u]);
            #pragma unroll
            for (int np = 0; np < 4; np++) {
                uint32_t kh4[4];
                ldsm_x4(kh4, sbase + (uint32_t)(OKH * 4) + bOff4 + (uint32_t)(np * 16 * AP * 4 + kk * 32));
                mma_tf32(S[2*np],   ah, kh4);
                mma_tf32(S[2*np],   al, kh4);
                mma_tf32(S[2*np+1], ah, kh4 + 2);
                mma_tf32(S[2*np+1], al, kh4 + 2);
            }
        }

        // ---- online softmax ----
        float mt0 = -INFINITY, mt1 = -INFINITY;
        #pragma unroll
        for (int nt = 0; nt < 8; nt++) {
            #pragma unroll
            for (int u = 0; u < 4; u++) S[nt][u] *= 0.125f;
            mt0 = fmaxf(mt0, fmaxf(S[nt][0], S[nt][1]));
            mt1 = fmaxf(mt1, fmaxf(S[nt][2], S[nt][3]));
        }
        mt0 = fmaxf(mt0, __shfl_xor_sync(0xffffffffu, mt0, 1));
        mt0 = fmaxf(mt0, __shfl_xor_sync(0xffffffffu, mt0, 2));
        mt1 = fmaxf(mt1, __shfl_xor_sync(0xffffffffu, mt1, 1));
        mt1 = fmaxf(mt1, __shfl_xor_sync(0xffffffffu, mt1, 2));
        const float mn0 = fmaxf(m0, mt0), mn1 = fmaxf(m1, mt1);
        const float a0 = __expf(m0 - mn0), a1 = __expf(m1 - mn1);
        float ls0 = 0.0f, ls1 = 0.0f;
        #pragma unroll
        for (int nt = 0; nt < 8; nt++) {
            S[nt][0] = __expf(S[nt][0] - mn0);
            S[nt][1] = __expf(S[nt][1] - mn0);
            S[nt][2] = __expf(S[nt][2] - mn1);
            S[nt][3] = __expf(S[nt][3] - mn1);
            ls0 += S[nt][0] + S[nt][1];
            ls1 += S[nt][2] + S[nt][3];
        }
        ls0 += __shfl_xor_sync(0xffffffffu, ls0, 1);
        ls0 += __shfl_xor_sync(0xffffffffu, ls0, 2);
        ls1 += __shfl_xor_sync(0xffffffffu, ls1, 1);
        ls1 += __shfl_xor_sync(0xffffffffu, ls1, 2);
        l0s = l0s * a0 + ls0;
        l1s = l1s * a1 + ls1;
        m0 = mn0; m1 = mn1;
        #pragma unroll
        for (int nt = 0; nt < 8; nt++) {
            O[nt][0] *= a0; O[nt][1] *= a0;
            O[nt][2] *= a1; O[nt][3] *= a1;
        }

        // ---- O += (Ph+Pl) Vh: P fragments via quad shuffles of S[kk] ----
        #pragma unroll
        for (int kk = 0; kk < 8; kk++) {
            const float v00 = __shfl_sync(0xffffffffu, S[kk][0], src0);
            const float v01 = __shfl_sync(0xffffffffu, S[kk][1], src0);
            const float v10 = __shfl_sync(0xffffffffu, S[kk][2], src0);
            const float v11 = __shfl_sync(0xffffffffu, S[kk][3], src0);
            const float w00 = __shfl_sync(0xffffffffu, S[kk][0], src1);
            const float w01 = __shfl_sync(0xffffffffu, S[kk][1], src1);
            const float w10 = __shfl_sync(0xffffffffu, S[kk][2], src1);
            const float w11 = __shfl_sync(0xffffffffu, S[kk][3], src1);
            const float a0f = (qc & 1) ? v01 : v00;
            const float a1f = (qc & 1) ? v11 : v10;
            const float a2f = (qc & 1) ? w01 : w00;
            const float a3f = (qc & 1) ? w11 : w10;
            uint32_t ph[4], pl[4];
            split2(a0f, ph[0], pl[0]);
            split2(a1f, ph[1], pl[1]);
            split2(a2f, ph[2], pl[2]);
            split2(a3f, ph[3], pl[3]);
            #pragma unroll
            for (int np = 0; np < 4; np++) {
                uint32_t vh4[4];
                ldsm_x4(vh4, sbase + (uint32_t)(OVH * 4) + bOff4 + (uint32_t)(np * 16 * AP * 4 + kk * 32));
                mma_tf32(O[2*np],   ph, vh4);
                mma_tf32(O[2*np],   pl, vh4);
                mma_tf32(O[2*np+1], ph, vh4 + 2);
                mma_tf32(O[2*np+1], pl, vh4 + 2);
            }
        }
    }

    const float inv0 = 1.0f / l0s, inv1 = 1.0f / l1s;
    #pragma unroll
    for (int nt = 0; nt < 8; nt++) {
        const int col = h * D_ + nt * 8 + 2 * qc;
        const size_t r0 = rowbase + mrow + qr;
        *(float2*)(out + r0 * C_ + col) =
            make_float2(tf32r(O[nt][0] * inv0), tf32r(O[nt][1] * inv0));
        *(float2*)(out + (r0 + 8) * C_ + col) =
            make_float2(tf32r(O[nt][2] * inv1), tf32r(O[nt][3] * inv1));
    }
}

// ---------------- host launcher -------------------------------------------
extern "C" void kernel_launch(void* const* d_in, const int* in_sizes, int n_in,
                              void* d_out, int out_size)
{
    (void)in_sizes; (void)n_in; (void)out_size;
    const float* x      = (const float*)d_in[0];
    const float* ln1_w  = (const float*)d_in[1];
    const float* ln1_b  = (const float*)d_in[2];
    const float* qkv_w  = (const float*)d_in[3];
    const float* proj_w = (const float*)d_in[4];
    const float* proj_b = (const float*)d_in[5];
    const float* ln2_w  = (const float*)d_in[6];
    const float* ln2_b  = (const float*)d_in[7];
    const float* fc1_w  = (const float*)d_in[8];
    const float* fc1_b  = (const float*)d_in[9];
    const float* fc2_w  = (const float*)d_in[10];
    const float* fc2_b  = (const float*)d_in[11];
    float* out = (float*)d_out;

    float *h1, *qkvb, *attn, *x2, *ln2o, *fc1o, *rw;
    cudaGetSymbolAddress((void**)&h1,   g_h1);
    cudaGetSymbolAddress((void**)&qkvb, g_qkv);
    cudaGetSymbolAddress((void**)&attn, g_attn);
    cudaGetSymbolAddress((void**)&x2,   g_x2);
    cudaGetSymbolAddress((void**)&ln2o, g_ln2);
    cudaGetSymbolAddress((void**)&fc1o, g_fc1);
    cudaGetSymbolAddress((void**)&rw,   g_rw);

    static bool attr_done = false;
    if (!attr_done) {
        cudaFuncSetAttribute(tc_gemm<0>, cudaFuncAttributeMaxDynamicSharedMemorySize, GSMEM);
        cudaFuncSetAttribute(tc_gemm<1>, cudaFuncAttributeMaxDynamicSharedMemorySize, GSMEM);
        cudaFuncSetAttribute(tc_gemm<2>, cudaFuncAttributeMaxDynamicSharedMemorySize, GSMEM);
        cudaFuncSetAttribute(tc_gemm<3>, cudaFuncAttributeMaxDynamicSharedMemorySize, GSMEM);
        cudaFuncSetAttribute(attn_mma,   cudaFuncAttributeMaxDynamicSharedMemorySize, ATT_SMEM);
        attr_done = true;
    }

    round_all_kernel<<<(RW_TOT/4 + 255)/256, 256>>>(qkv_w, proj_w, fc1_w, fc2_w, rw);

    ln_kernel<<<M_, 256>>>(x, ln1_w, ln1_b, h1);
    tc_gemm<0><<<dim3(3*C_/128, M_/128), 128, GSMEM>>>(h1, rw + RW_QKV, nullptr, nullptr, qkvb, M_, 3*C_, C_);
    attn_mma<<<dim3(4, B_*H_), 256, ATT_SMEM>>>(qkvb, attn);
    tc_gemm<1><<<dim3(C_/128, M_/128), 128, GSMEM>>>(attn, rw + RW_PROJ, proj_b, nullptr, x2, M_, C_, C_);
    ln_kernel<<<M_, 256>>>(x2, ln2_w, ln2_b, ln2o);
    tc_gemm<2><<<dim3(HID_/128, M_/128), 128, GSMEM>>>(ln2o, rw + RW_FC1, fc1_b, nullptr, fc1o, M_, HID_, C_);
    tc_gemm<3><<<dim3(C_/128, M_/128), 128, GSMEM>>>(fc1o, rw + RW_FC2, fc2_b, x2, out, M_, C_, HID_);
}

// round 14
// speedup vs baseline: 1.7382x; 1.1409x over previous
#include <cuda_runtime.h>
#include <cuda_fp16.h>
#include <math.h>
#include <stdint.h>

#define B_   32
#define N_   512
#define C_   768
#define H_   12
#define D_   64
#define HID_ 3072
#define M_   (B_*N_)   // 16384 rows

// ---------------- scratch (device globals; no allocation allowed) ----------
__device__ __half g_h1  [(size_t)M_ * C_];        // LN1 out (fp16)
__device__ float  g_qkv [(size_t)M_ * 3 * C_];    // QKV out (fp32: Q needs split)
__device__ __half g_attn[(size_t)M_ * C_];        // attention out (fp16)
__device__ float  g_x2  [(size_t)M_ * C_];        // residual stream (fp32)
__device__ __half g_ln2 [(size_t)M_ * C_];        // LN2 out (fp16)
__device__ __half g_fc1 [(size_t)M_ * HID_];      // FC1+GELU out (fp16)
// fp16 weights: qkv_w | proj_w | fc1_w | fc2_w
#define RW_QKV 0
#define RW_PROJ (3*C_*C_)
#define RW_FC1  (RW_PROJ + C_*C_)
#define RW_FC2  (RW_FC1 + HID_*C_)
#define RW_TOT  (RW_FC2 + C_*HID_)
__device__ __half g_rw[(size_t)RW_TOT];

// ================= small helpers ===========================================
__device__ __forceinline__ void cp16(uint32_t saddr, const void* g) {
    asm volatile("cp.async.cg.shared.global [%0], [%1], 16;" :: "r"(saddr), "l"(g) : "memory");
}
__device__ __forceinline__ uint32_t smem_u32(const void* p) {
    uint32_t a;
    asm("{ .reg .u64 t; cvta.to.shared.u64 t, %1; cvt.u32.u64 %0, t; }" : "=r"(a) : "l"(p));
    return a;
}
__device__ __forceinline__ uint32_t h2u(__half2 h) { return *(uint32_t*)&h; }
__device__ __forceinline__ void mma_f16(float* c, const uint32_t* a, const uint32_t* b) {
    asm volatile("mma.sync.aligned.m16n8k16.row.col.f32.f16.f16.f32 "
                 "{%0,%1,%2,%3}, {%4,%5,%6,%7}, {%8,%9}, {%0,%1,%2,%3};"
                 : "+f"(c[0]), "+f"(c[1]), "+f"(c[2]), "+f"(c[3])
                 : "r"(a[0]), "r"(a[1]), "r"(a[2]), "r"(a[3]), "r"(b[0]), "r"(b[1]));
}
__device__ __forceinline__ void ldsm_x4(uint32_t* r, uint32_t addr) {
    asm volatile("ldmatrix.sync.aligned.m8n8.x4.shared.b16 {%0,%1,%2,%3}, [%4];"
                 : "=r"(r[0]), "=r"(r[1]), "=r"(r[2]), "=r"(r[3]) : "r"(addr));
}

// ================= weight fp16 pre-round (single kernel) ===================
__global__ void __launch_bounds__(256) round_all_kernel(const float* __restrict__ w0,
                                                        const float* __restrict__ w1,
                                                        const float* __restrict__ w2,
                                                        const float* __restrict__ w3,
                                                        __half* __restrict__ out)
{
    const size_t i = ((size_t)blockIdx.x * 256 + threadIdx.x) * 4;
    if (i >= (size_t)RW_TOT) return;
    const float* src;
    size_t off;
    if (i < (size_t)RW_PROJ)      { src = w0; off = i; }
    else if (i < (size_t)RW_FC1)  { src = w1; off = i - RW_PROJ; }
    else if (i < (size_t)RW_FC2)  { src = w2; off = i - RW_FC1; }
    else                          { src = w3; off = i - RW_FC2; }
    float4 v = *(const float4*)(src + off);
    *(__half2*)(out + i)     = __floats2half2_rn(v.x, v.y);
    *(__half2*)(out + i + 2) = __floats2half2_rn(v.z, v.w);
}

// ================= fp16 mma.sync GEMM ======================================
// CTA 128x128, 4 warps, warp tile 64x64, BK=64 halfs (4 k16 chunks/stage).
// smem row stride 72 halfs (144B: conflict-free, 16B-aligned). 3-stage cp.async.
// MODE 0: plain, fp32 out; 1: 2*(acc+bias), fp32 out; 2: gelu(acc+bias), fp16 out;
// MODE 3: acc+bias+res, fp32 out.
#define BKH 64
#define ROWB 144
#define AT_BYTES (128 * ROWB)        // 18432
#define STAGE_B  (2 * AT_BYTES)      // 36864
#define GSMEM    (3 * STAGE_B)       // 110592

template <int MODE>
__global__ void __launch_bounds__(128) tc_gemm(const __half* __restrict__ A,
                                               const __half* __restrict__ W,
                                               const float* __restrict__ bias,
                                               const float* __restrict__ res,
                                               void* __restrict__ CoutV,
                                               int M, int Nn, int K)
{
    extern __shared__ char smem[];
    const uint32_t sbase = smem_u32(smem);
    const int tid = threadIdx.x;
    const int bm = blockIdx.y, bn = blockIdx.x;

    const __half* Ab = A + (size_t)bm * 128 * K;
    const __half* Wb = W + (size_t)bn * 128 * K;
    const int nk = K / BKH;

    auto load_stage = [&](int slot, int k0) {
        const uint32_t sA = sbase + slot * STAGE_B;
        const uint32_t sB = sA + AT_BYTES;
        #pragma unroll
        for (int t = 0; t < 8; t++) {
            const int c = tid + 128 * t;       // 0..1023
            const int row = c >> 3;
            const int seg = c & 7;             // 16-byte (8-half) chunk
            const uint32_t off = (uint32_t)(row * ROWB + seg * 16);
            cp16(sA + off, Ab + (size_t)row * K + k0 + seg * 8);
            cp16(sB + off, Wb + (size_t)row * K + k0 + seg * 8);
        }
        asm volatile("cp.async.commit_group;" ::: "memory");
    };

    load_stage(0, 0);
    load_stage(1, BKH);

    const int wid = tid >> 5, lane = tid & 31;
    const int wm = (wid >> 1) * 64;
    const int wn = (wid & 1) * 64;
    const int qr = lane >> 2, qc = lane & 3;

    const int l7 = lane & 7;
    const uint32_t aOff = (uint32_t)((wm + l7 + ((lane >> 3) & 1) * 8) * ROWB
                                     + ((lane >> 4) & 1) * 16);
    const uint32_t bOff = (uint32_t)((wn + l7 + ((lane >> 4) & 1) * 8) * ROWB
                                     + ((lane >> 3) & 1) * 16);

    float acc[4][8][4];
    #pragma unroll
    for (int mi = 0; mi < 4; mi++)
        #pragma unroll
        for (int ni = 0; ni < 8; ni++)
            #pragma unroll
            for (int u = 0; u < 4; u++) acc[mi][ni][u] = 0.0f;

    int slot = 0, slot2 = 2;
    for (int i = 0; i < nk; i++) {
        if (i == nk - 1) asm volatile("cp.async.wait_group 0;" ::: "memory");
        else             asm volatile("cp.async.wait_group 1;" ::: "memory");
        __syncthreads();
        if (i + 2 < nk) load_stage(slot2, (i + 2) * BKH);

        const uint32_t sA = sbase + slot * STAGE_B;
        const uint32_t sB = sA + AT_BYTES;
        #pragma unroll
        for (int kc = 0; kc < 4; kc++) {          // k16 chunks: kc*32 bytes
            uint32_t af[4][4], bf[4][4];
            #pragma unroll
            for (int mi = 0; mi < 4; mi++)
                ldsm_x4(af[mi], sA + aOff + (uint32_t)(mi * 16 * ROWB) + (uint32_t)(kc * 32));
            #pragma unroll
            for (int np = 0; np < 4; np++)
                ldsm_x4(bf[np], sB + bOff + (uint32_t)(np * 16 * ROWB) + (uint32_t)(kc * 32));
            #pragma unroll
            for (int mi = 0; mi < 4; mi++)
                #pragma unroll
                for (int ni = 0; ni < 8; ni++)
                    mma_f16(acc[mi][ni], af[mi], &bf[ni >> 1][(ni & 1) * 2]);
        }
        slot = (slot + 1 == 3) ? 0 : slot + 1;
        slot2 = (slot2 + 1 == 3) ? 0 : slot2 + 1;
    }

    #pragma unroll
    for (int mi = 0; mi < 4; mi++) {
        #pragma unroll
        for (int ni = 0; ni < 8; ni++) {
            const int col = bn * 128 + wn + ni * 8 + 2 * qc;
            #pragma unroll
            for (int half_ = 0; half_ < 2; half_++) {
                const size_t row = (size_t)bm * 128 + wm + mi * 16 + qr + half_ * 8;
                float v0 = acc[mi][ni][half_ * 2 + 0];
                float v1 = acc[mi][ni][half_ * 2 + 1];
                if (MODE == 1) {
                    v0 = 2.0f * (v0 + bias[col]);
                    v1 = 2.0f * (v1 + bias[col + 1]);
                } else if (MODE == 2) {
                    v0 += bias[col];
                    v1 += bias[col + 1];
                    v0 = 0.5f * v0 * (1.0f + erff(v0 * 0.70710678118654752f));
                    v1 = 0.5f * v1 * (1.0f + erff(v1 * 0.70710678118654752f));
                } else if (MODE == 3) {
                    const float* rr = res + row * Nn + col;
                    v0 += bias[col] + rr[0];
                    v1 += bias[col + 1] + rr[1];
                }
                if (MODE == 2) {
                    *(__half2*)((__half*)CoutV + row * Nn + col) = __floats2half2_rn(v0, v1);
                } else {
                    *(float2*)((float*)CoutV + row * Nn + col) = make_float2(v0, v1);
                }
            }
        }
    }
}

// ---------------- fused LayerNorm (fp16 output) ----------------------------
__global__ void __launch_bounds__(256) ln_kernel(const float* __restrict__ x,
                                                 const float* __restrict__ w,
                                                 const float* __restrict__ b,
                                                 __half* __restrict__ out)
{
    __shared__ float red[8];
    const int row = blockIdx.x;
    const int t   = threadIdx.x;
    const float* xr = x + (size_t)row * C_;

    float v0 = xr[t], v1 = xr[t + 256], v2 = xr[t + 512];
    float s = v0 + v1 + v2;
    #pragma unroll
    for (int o = 16; o; o >>= 1) s += __shfl_xor_sync(0xffffffffu, s, o);
    if ((t & 31) == 0) red[t >> 5] = s;
    __syncthreads();
    float tot = red[0]+red[1]+red[2]+red[3]+red[4]+red[5]+red[6]+red[7];
    const float mu = tot * (1.0f / C_);

    float d0 = v0 - mu, d1 = v1 - mu, d2 = v2 - mu;
    float q = d0*d0 + d1*d1 + d2*d2;
    #pragma unroll
    for (int o = 16; o; o >>= 1) q += __shfl_xor_sync(0xffffffffu, q, o);
    __syncthreads();
    if ((t & 31) == 0) red[t >> 5] = q;
    __syncthreads();
    float var = (red[0]+red[1]+red[2]+red[3]+red[4]+red[5]+red[6]+red[7]) * (1.0f / C_);
    const float rstd = rsqrtf(var + 1e-5f);

    __half* orow = out + (size_t)row * C_;
    orow[t]       = __float2half_rn(d0 * rstd * w[t]       + b[t]);
    orow[t + 256] = __float2half_rn(d1 * rstd * w[t + 256] + b[t + 256]);
    orow[t + 512] = __float2half_rn(d2 * rstd * w[t + 512] + b[t + 512]);
}

// ================= flash attention fp16: split-A, k16 mma ==================
// S = (Qh+Ql)*Kh, O += (Ph+Pl)*Vh. Q split once into smem (half hi/lo);
// K/V hi-only half. P fragments built in registers (no shuffles: fp16 A-frag
// k-pair layout == S accumulator fragment layout).
#define ASTR 72                       // halfs per row (144 B)
#define QH_B 0
#define QL_B (128*ASTR*2)             // 18432
#define KH_B (2*128*ASTR*2)           // 36864
#define VT_B (KH_B + 64*ASTR*2)       // 46080
#define ATT_SMEM (VT_B + 64*ASTR*2)   // 55296 B

__global__ void __launch_bounds__(256, 2) attn_mma(const float* __restrict__ qkv,
                                                   __half* __restrict__ out)
{
    extern __shared__ char smc[];
    const uint32_t sbase = smem_u32(smc);
    __half* Qh  = (__half*)(smc + QH_B);
    __half* Ql  = (__half*)(smc + QL_B);
    __half* Kh  = (__half*)(smc + KH_B);
    __half* Vth = (__half*)(smc + VT_B);

    const int qt = blockIdx.x;
    const int bh = blockIdx.y;
    const int h  = bh % H_;
    const int b  = bh / H_;
    const int tid = threadIdx.x;
    const int w = tid >> 5, lane = tid & 31;
    const int qr = lane >> 2, qc = lane & 3;
    const int mrow = w * 16;
    const size_t rowbase = (size_t)b * N_ + (size_t)qt * 128;

    const int l7 = lane & 7;
    const uint32_t aOff = (uint32_t)((mrow + l7 + ((lane >> 3) & 1) * 8) * ASTR * 2
                                     + ((lane >> 4) & 1) * 16);
    const uint32_t bOff = (uint32_t)((l7 + ((lane >> 4) & 1) * 8) * ASTR * 2
                                     + ((lane >> 3) & 1) * 16);

    // ---- stage + split Q once (128 x 64) ----
    #pragma unroll
    for (int t = 0; t < 8; t++) {
        int i = tid + t * 256;
        int row = i >> 4, c4 = (i & 15) * 4;
        float4 v = *(const float4*)(qkv + (rowbase + row) * (3 * C_) + h * D_ + c4);
        __half2 h01 = __floats2half2_rn(v.x, v.y);
        __half2 h23 = __floats2half2_rn(v.z, v.w);
        float2 f01 = __half22float2(h01);
        float2 f23 = __half22float2(h23);
        __half2 l01 = __floats2half2_rn(v.x - f01.x, v.y - f01.y);
        __half2 l23 = __floats2half2_rn(v.z - f23.x, v.w - f23.y);
        *(__half2*)(Qh + row * ASTR + c4)     = h01;
        *(__half2*)(Qh + row * ASTR + c4 + 2) = h23;
        *(__half2*)(Ql + row * ASTR + c4)     = l01;
        *(__half2*)(Ql + row * ASTR + c4 + 2) = l23;
    }

    float m0 = -INFINITY, m1 = -INFINITY, l0s = 0.0f, l1s = 0.0f;
    float O[8][4];
    #pragma unroll
    for (int nt = 0; nt < 8; nt++)
        #pragma unroll
        for (int u = 0; u < 4; u++) O[nt][u] = 0.0f;

    for (int kt = 0; kt < 8; kt++) {
        __syncthreads();   // Q writes (kt==0) + prior tile reads
        // ---- load K (hi-only half) and V transposed (hi-only half) ----
        #pragma unroll
        for (int t = 0; t < 4; t++) {
            int i = tid + t * 256;
            int row = i >> 4, c4 = (i & 15) * 4;
            const float* src = qkv + ((size_t)b * N_ + kt * 64 + row) * (3 * C_) + C_ + h * D_ + c4;
            float4 kv = *(const float4*)src;
            float4 vv = *(const float4*)(src + C_);
            *(__half2*)(Kh + row * ASTR + c4)     = __floats2half2_rn(kv.x, kv.y);
            *(__half2*)(Kh + row * ASTR + c4 + 2) = __floats2half2_rn(kv.z, kv.w);
            Vth[(c4 + 0) * ASTR + row] = __float2half_rn(vv.x);
            Vth[(c4 + 1) * ASTR + row] = __float2half_rn(vv.y);
            Vth[(c4 + 2) * ASTR + row] = __float2half_rn(vv.z);
            Vth[(c4 + 3) * ASTR + row] = __float2half_rn(vv.w);
        }
        __syncthreads();

        // ---- S = (Qh+Ql) Kh^T  (k16 chunks) ----
        float S[8][4];
        #pragma unroll
        for (int nt = 0; nt < 8; nt++)
            #pragma unroll
            for (int u = 0; u < 4; u++) S[nt][u] = 0.0f;

        #pragma unroll
        for (int kk = 0; kk < 4; kk++) {
            uint32_t ah[4], al[4];
            ldsm_x4(ah, sbase + (uint32_t)QH_B + aOff + (uint32_t)(kk * 32));
            ldsm_x4(al, sbase + (uint32_t)QL_B + aOff + (uint32_t)(kk * 32));
            #pragma unroll
            for (int np = 0; np < 4; np++) {
                uint32_t kh4[4];
                ldsm_x4(kh4, sbase + (uint32_t)KH_B + bOff + (uint32_t)(np * 16 * ASTR * 2 + kk * 32));
                mma_f16(S[2*np],   ah, kh4);
                mma_f16(S[2*np],   al, kh4);
                mma_f16(S[2*np+1], ah, kh4 + 2);
                mma_f16(S[2*np+1], al, kh4 + 2);
            }
        }

        // ---- online softmax ----
        float mt0 = -INFINITY, mt1 = -INFINITY;
        #pragma unroll
        for (int nt = 0; nt < 8; nt++) {
            #pragma unroll
            for (int u = 0; u < 4; u++) S[nt][u] *= 0.125f;
            mt0 = fmaxf(mt0, fmaxf(S[nt][0], S[nt][1]));
            mt1 = fmaxf(mt1, fmaxf(S[nt][2], S[nt][3]));
        }
        mt0 = fmaxf(mt0, __shfl_xor_sync(0xffffffffu, mt0, 1));
        mt0 = fmaxf(mt0, __shfl_xor_sync(0xffffffffu, mt0, 2));
        mt1 = fmaxf(mt1, __shfl_xor_sync(0xffffffffu, mt1, 1));
        mt1 = fmaxf(mt1, __shfl_xor_sync(0xffffffffu, mt1, 2));
        const float mn0 = fmaxf(m0, mt0), mn1 = fmaxf(m1, mt1);
        const float a0 = __expf(m0 - mn0), a1 = __expf(m1 - mn1);
        float ls0 = 0.0f, ls1 = 0.0f;
        #pragma unroll
        for (int nt = 0; nt < 8; nt++) {
            S[nt][0] = __expf(S[nt][0] - mn0);
            S[nt][1] = __expf(S[nt][1] - mn0);
            S[nt][2] = __expf(S[nt][2] - mn1);
            S[nt][3] = __expf(S[nt][3] - mn1);
            ls0 += S[nt][0] + S[nt][1];
            ls1 += S[nt][2] + S[nt][3];
        }
        ls0 += __shfl_xor_sync(0xffffffffu, ls0, 1);
        ls0 += __shfl_xor_sync(0xffffffffu, ls0, 2);
        ls1 += __shfl_xor_sync(0xffffffffu, ls1, 1);
        ls1 += __shfl_xor_sync(0xffffffffu, ls1, 2);
        l0s = l0s * a0 + ls0;
        l1s = l1s * a1 + ls1;
        m0 = mn0; m1 = mn1;
        #pragma unroll
        for (int nt = 0; nt < 8; nt++) {
            O[nt][0] *= a0; O[nt][1] *= a0;
            O[nt][2] *= a1; O[nt][3] *= a1;
        }

        // ---- O += (Ph+Pl) Vh: P A-frags built directly from S regs ----
        #pragma unroll
        for (int j = 0; j < 4; j++) {             // key16 chunks
            __half2 h0 = __floats2half2_rn(S[2*j][0],   S[2*j][1]);
            __half2 h1 = __floats2half2_rn(S[2*j][2],   S[2*j][3]);
            __half2 h2 = __floats2half2_rn(S[2*j+1][0], S[2*j+1][1]);
            __half2 h3 = __floats2half2_rn(S[2*j+1][2], S[2*j+1][3]);
            float2 f0 = __half22float2(h0), f1 = __half22float2(h1);
            float2 f2 = __half22float2(h2), f3 = __half22float2(h3);
            uint32_t ph[4] = { h2u(h0), h2u(h1), h2u(h2), h2u(h3) };
            uint32_t pl[4] = {
                h2u(__floats2half2_rn(S[2*j][0]   - f0.x, S[2*j][1]   - f0.y)),
                h2u(__floats2half2_rn(S[2*j][2]   - f1.x, S[2*j][3]   - f1.y)),
                h2u(__floats2half2_rn(S[2*j+1][0] - f2.x, S[2*j+1][1] - f2.y)),
                h2u(__floats2half2_rn(S[2*j+1][2] - f3.x, S[2*j+1][3] - f3.y))
            };
            #pragma unroll
            for (int np = 0; np < 4; np++) {
                uint32_t vh4[4];
                ldsm_x4(vh4, sbase + (uint32_t)VT_B + bOff + (uint32_t)(np * 16 * ASTR * 2 + j * 32));
                mma_f16(O[2*np],   ph, vh4);
                mma_f16(O[2*np],   pl, vh4);
                mma_f16(O[2*np+1], ph, vh4 + 2);
                mma_f16(O[2*np+1], pl, vh4 + 2);
            }
        }
    }

    const float inv0 = 1.0f / l0s, inv1 = 1.0f / l1s;
    #pragma unroll
    for (int nt = 0; nt < 8; nt++) {
        const int col = h * D_ + nt * 8 + 2 * qc;
        const size_t r0 = rowbase + mrow + qr;
        *(__half2*)(out + r0 * C_ + col) =
            __floats2half2_rn(O[nt][0] * inv0, O[nt][1] * inv0);
        *(__half2*)(out + (r0 + 8) * C_ + col) =
            __floats2half2_rn(O[nt][2] * inv1, O[nt][3] * inv1);
    }
}

// ---------------- host launcher -------------------------------------------
extern "C" void kernel_launch(void* const* d_in, const int* in_sizes, int n_in,
                              void* d_out, int out_size)
{
    (void)in_sizes; (void)n_in; (void)out_size;
    const float* x      = (const float*)d_in[0];
    const float* ln1_w  = (const float*)d_in[1];
    const float* ln1_b  = (const float*)d_in[2];
    const float* qkv_w  = (const float*)d_in[3];
    const float* proj_w = (const float*)d_in[4];
    const float* proj_b = (const float*)d_in[5];
    const float* ln2_w  = (const float*)d_in[6];
    const float* ln2_b  = (const float*)d_in[7];
    const float* fc1_w  = (const float*)d_in[8];
    const float* fc1_b  = (const float*)d_in[9];
    const float* fc2_w  = (const float*)d_in[10];
    const float* fc2_b  = (const float*)d_in[11];
    float* out = (float*)d_out;

    __half *h1, *attn, *ln2o, *fc1o, *rw;
    float *qkvb, *x2;
    cudaGetSymbolAddress((void**)&h1,   g_h1);
    cudaGetSymbolAddress((void**)&qkvb, g_qkv);
    cudaGetSymbolAddress((void**)&attn, g_attn);
    cudaGetSymbolAddress((void**)&x2,   g_x2);
    cudaGetSymbolAddress((void**)&ln2o, g_ln2);
    cudaGetSymbolAddress((void**)&fc1o, g_fc1);
    cudaGetSymbolAddress((void**)&rw,   g_rw);

    static bool attr_done = false;
    if (!attr_done) {
        cudaFuncSetAttribute(tc_gemm<0>, cudaFuncAttributeMaxDynamicSharedMemorySize, GSMEM);
        cudaFuncSetAttribute(tc_gemm<1>, cudaFuncAttributeMaxDynamicSharedMemorySize, GSMEM);
        cudaFuncSetAttribute(tc_gemm<2>, cudaFuncAttributeMaxDynamicSharedMemorySize, GSMEM);
        cudaFuncSetAttribute(tc_gemm<3>, cudaFuncAttributeMaxDynamicSharedMemorySize, GSMEM);
        cudaFuncSetAttribute(attn_mma,   cudaFuncAttributeMaxDynamicSharedMemorySize, ATT_SMEM);
        attr_done = true;
    }

    round_all_kernel<<<(RW_TOT/4 + 255)/256, 256>>>(qkv_w, proj_w, fc1_w, fc2_w, rw);

    ln_kernel<<<M_, 256>>>(x, ln1_w, ln1_b, h1);
    tc_gemm<0><<<dim3(3*C_/128, M_/128), 128, GSMEM>>>(h1, rw + RW_QKV, nullptr, nullptr, qkvb, M_, 3*C_, C_);
    attn_mma<<<dim3(4, B_*H_), 256, ATT_SMEM>>>(qkvb, attn);
    tc_gemm<1><<<dim3(C_/128, M_/128), 128, GSMEM>>>(attn, rw + RW_PROJ, proj_b, nullptr, x2, M_, C_, C_);
    ln_kernel<<<M_, 256>>>(x2, ln2_w, ln2_b, ln2o);
    tc_gemm<2><<<dim3(HID_/128, M_/128), 128, GSMEM>>>(ln2o, rw + RW_FC1, fc1_b, nullptr, fc1o, M_, HID_, C_);
    tc_gemm<3><<<dim3(C_/128, M_/128), 128, GSMEM>>>(fc1o, rw + RW_FC2, fc2_b, x2, out, M_, C_, HID_);
}

// round 15
// speedup vs baseline: 2.7874x; 1.6036x over previous
#include <cuda_runtime.h>
#include <cuda_fp16.h>
#include <math.h>
#include <stdint.h>

#define B_   32
#define N_   512
#define C_   768
#define H_   12
#define D_   64
#define HID_ 3072
#define M_   (B_*N_)   // 16384 rows

// ---------------- scratch (device globals; no allocation allowed) ----------
__device__ __half g_h1  [(size_t)M_ * C_];        // LN1 out (fp16)
__device__ __half g_qh  [(size_t)M_ * C_];        // Q hi (fp16)
__device__ __half g_ql  [(size_t)M_ * C_];        // Q lo (fp16)
__device__ __half g_kv  [(size_t)M_ * 2 * C_];    // K | V (fp16)
__device__ __half g_attn[(size_t)M_ * C_];        // attention out (fp16)
__device__ float  g_x2  [(size_t)M_ * C_];        // residual stream (fp32)
__device__ __half g_ln2 [(size_t)M_ * C_];        // LN2 out (fp16)
__device__ __half g_fc1 [(size_t)M_ * HID_];      // FC1+GELU out (fp16)
// fp16 weights: qkv_w | proj_w | fc1_w | fc2_w
#define RW_QKV 0
#define RW_PROJ (3*C_*C_)
#define RW_FC1  (RW_PROJ + C_*C_)
#define RW_FC2  (RW_FC1 + HID_*C_)
#define RW_TOT  (RW_FC2 + C_*HID_)
__device__ __half g_rw[(size_t)RW_TOT];

// ================= small helpers ===========================================
__device__ __forceinline__ void cp16(uint32_t saddr, const void* g) {
    asm volatile("cp.async.cg.shared.global [%0], [%1], 16;" :: "r"(saddr), "l"(g) : "memory");
}
__device__ __forceinline__ uint32_t smem_u32(const void* p) {
    uint32_t a;
    asm("{ .reg .u64 t; cvta.to.shared.u64 t, %1; cvt.u32.u64 %0, t; }" : "=r"(a) : "l"(p));
    return a;
}
__device__ __forceinline__ uint32_t h2u(__half2 h) { return *(uint32_t*)&h; }
__device__ __forceinline__ void mma_f16(float* c, const uint32_t* a, const uint32_t* b) {
    asm volatile("mma.sync.aligned.m16n8k16.row.col.f32.f16.f16.f32 "
                 "{%0,%1,%2,%3}, {%4,%5,%6,%7}, {%8,%9}, {%0,%1,%2,%3};"
                 : "+f"(c[0]), "+f"(c[1]), "+f"(c[2]), "+f"(c[3])
                 : "r"(a[0]), "r"(a[1]), "r"(a[2]), "r"(a[3]), "r"(b[0]), "r"(b[1]));
}
__device__ __forceinline__ void ldsm_x4(uint32_t* r, uint32_t addr) {
    asm volatile("ldmatrix.sync.aligned.m8n8.x4.shared.b16 {%0,%1,%2,%3}, [%4];"
                 : "=r"(r[0]), "=r"(r[1]), "=r"(r[2]), "=r"(r[3]) : "r"(addr));
}
__device__ __forceinline__ void ldsm_x4t(uint32_t* r, uint32_t addr) {
    asm volatile("ldmatrix.sync.aligned.m8n8.x4.trans.shared.b16 {%0,%1,%2,%3}, [%4];"
                 : "=r"(r[0]), "=r"(r[1]), "=r"(r[2]), "=r"(r[3]) : "r"(addr));
}

// ================= weight fp16 pre-round (single kernel) ===================
__global__ void __launch_bounds__(256) round_all_kernel(const float* __restrict__ w0,
                                                        const float* __restrict__ w1,
                                                        const float* __restrict__ w2,
                                                        const float* __restrict__ w3,
                                                        __half* __restrict__ out)
{
    const size_t i = ((size_t)blockIdx.x * 256 + threadIdx.x) * 4;
    if (i >= (size_t)RW_TOT) return;
    const float* src;
    size_t off;
    if (i < (size_t)RW_PROJ)      { src = w0; off = i; }
    else if (i < (size_t)RW_FC1)  { src = w1; off = i - RW_PROJ; }
    else if (i < (size_t)RW_FC2)  { src = w2; off = i - RW_FC1; }
    else                          { src = w3; off = i - RW_FC2; }
    float4 v = *(const float4*)(src + off);
    *(__half2*)(out + i)     = __floats2half2_rn(v.x, v.y);
    *(__half2*)(out + i + 2) = __floats2half2_rn(v.z, v.w);
}

// ================= fp16 mma.sync GEMM ======================================
// CTA 128x128, 4 warps, warp tile 64x64, BK=64 halfs. 3-stage cp.async.
// MODE 0: QKV — Q cols (bn<6) -> qh/ql split halves; K/V cols -> kv half.
// MODE 1: 2*(acc+bias) fp32; MODE 2: gelu(acc+bias) fp16; MODE 3: acc+bias+res fp32.
#define BKH 64
#define ROWB 144
#define AT_BYTES (128 * ROWB)
#define STAGE_B  (2 * AT_BYTES)
#define GSMEM    (3 * STAGE_B)

template <int MODE>
__global__ void __launch_bounds__(128) tc_gemm(const __half* __restrict__ A,
                                               const __half* __restrict__ W,
                                               const float* __restrict__ bias,
                                               const float* __restrict__ res,
                                               void* __restrict__ out0,
                                               void* __restrict__ out1,
                                               void* __restrict__ out2,
                                               int M, int Nn, int K)
{
    extern __shared__ char smem[];
    const uint32_t sbase = smem_u32(smem);
    const int tid = threadIdx.x;
    const int bm = blockIdx.y, bn = blockIdx.x;

    const __half* Ab = A + (size_t)bm * 128 * K;
    const __half* Wb = W + (size_t)bn * 128 * K;
    const int nk = K / BKH;

    auto load_stage = [&](int slot, int k0) {
        const uint32_t sA = sbase + slot * STAGE_B;
        const uint32_t sB = sA + AT_BYTES;
        #pragma unroll
        for (int t = 0; t < 8; t++) {
            const int c = tid + 128 * t;
            const int row = c >> 3;
            const int seg = c & 7;
            const uint32_t off = (uint32_t)(row * ROWB + seg * 16);
            cp16(sA + off, Ab + (size_t)row * K + k0 + seg * 8);
            cp16(sB + off, Wb + (size_t)row * K + k0 + seg * 8);
        }
        asm volatile("cp.async.commit_group;" ::: "memory");
    };

    load_stage(0, 0);
    load_stage(1, BKH);

    const int wid = tid >> 5, lane = tid & 31;
    const int wm = (wid >> 1) * 64;
    const int wn = (wid & 1) * 64;
    const int qr = lane >> 2, qc = lane & 3;

    const int l7 = lane & 7;
    const uint32_t aOff = (uint32_t)((wm + l7 + ((lane >> 3) & 1) * 8) * ROWB
                                     + ((lane >> 4) & 1) * 16);
    const uint32_t bOff = (uint32_t)((wn + l7 + ((lane >> 4) & 1) * 8) * ROWB
                                     + ((lane >> 3) & 1) * 16);

    float acc[4][8][4];
    #pragma unroll
    for (int mi = 0; mi < 4; mi++)
        #pragma unroll
        for (int ni = 0; ni < 8; ni++)
            #pragma unroll
            for (int u = 0; u < 4; u++) acc[mi][ni][u] = 0.0f;

    int slot = 0, slot2 = 2;
    for (int i = 0; i < nk; i++) {
        if (i == nk - 1) asm volatile("cp.async.wait_group 0;" ::: "memory");
        else             asm volatile("cp.async.wait_group 1;" ::: "memory");
        __syncthreads();
        if (i + 2 < nk) load_stage(slot2, (i + 2) * BKH);

        const uint32_t sA = sbase + slot * STAGE_B;
        const uint32_t sB = sA + AT_BYTES;
        #pragma unroll
        for (int kc = 0; kc < 4; kc++) {
            uint32_t af[4][4], bf[4][4];
            #pragma unroll
            for (int mi = 0; mi < 4; mi++)
                ldsm_x4(af[mi], sA + aOff + (uint32_t)(mi * 16 * ROWB) + (uint32_t)(kc * 32));
            #pragma unroll
            for (int np = 0; np < 4; np++)
                ldsm_x4(bf[np], sB + bOff + (uint32_t)(np * 16 * ROWB) + (uint32_t)(kc * 32));
            #pragma unroll
            for (int mi = 0; mi < 4; mi++)
                #pragma unroll
                for (int ni = 0; ni < 8; ni++)
                    mma_f16(acc[mi][ni], af[mi], &bf[ni >> 1][(ni & 1) * 2]);
        }
        slot = (slot + 1 == 3) ? 0 : slot + 1;
        slot2 = (slot2 + 1 == 3) ? 0 : slot2 + 1;
    }

    #pragma unroll
    for (int mi = 0; mi < 4; mi++) {
        #pragma unroll
        for (int ni = 0; ni < 8; ni++) {
            const int col = bn * 128 + wn + ni * 8 + 2 * qc;
            #pragma unroll
            for (int half_ = 0; half_ < 2; half_++) {
                const size_t row = (size_t)bm * 128 + wm + mi * 16 + qr + half_ * 8;
                float v0 = acc[mi][ni][half_ * 2 + 0];
                float v1 = acc[mi][ni][half_ * 2 + 1];
                if (MODE == 0) {
                    __half2 hv = __floats2half2_rn(v0, v1);
                    if (bn < 6) {
                        float2 f = __half22float2(hv);
                        __half2 lv = __floats2half2_rn(v0 - f.x, v1 - f.y);
                        *(__half2*)((__half*)out0 + row * C_ + col) = hv;
                        *(__half2*)((__half*)out1 + row * C_ + col) = lv;
                    } else {
                        *(__half2*)((__half*)out2 + row * (2 * C_) + (col - C_)) = hv;
                    }
                } else if (MODE == 1) {
                    v0 = 2.0f * (v0 + bias[col]);
                    v1 = 2.0f * (v1 + bias[col + 1]);
                    *(float2*)((float*)out0 + row * Nn + col) = make_float2(v0, v1);
                } else if (MODE == 2) {
                    v0 += bias[col];
                    v1 += bias[col + 1];
                    v0 = 0.5f * v0 * (1.0f + erff(v0 * 0.70710678118654752f));
                    v1 = 0.5f * v1 * (1.0f + erff(v1 * 0.70710678118654752f));
                    *(__half2*)((__half*)out0 + row * Nn + col) = __floats2half2_rn(v0, v1);
                } else {
                    const float* rr = res + row * Nn + col;
                    v0 += bias[col] + rr[0];
                    v1 += bias[col + 1] + rr[1];
                    *(float2*)((float*)out0 + row * Nn + col) = make_float2(v0, v1);
                }
            }
        }
    }
}

// ---------------- fused LayerNorm (fp16 output) ----------------------------
__global__ void __launch_bounds__(256) ln_kernel(const float* __restrict__ x,
                                                 const float* __restrict__ w,
                                                 const float* __restrict__ b,
                                                 __half* __restrict__ out)
{
    __shared__ float red[8];
    const int row = blockIdx.x;
    const int t   = threadIdx.x;
    const float* xr = x + (size_t)row * C_;

    float v0 = xr[t], v1 = xr[t + 256], v2 = xr[t + 512];
    float s = v0 + v1 + v2;
    #pragma unroll
    for (int o = 16; o; o >>= 1) s += __shfl_xor_sync(0xffffffffu, s, o);
    if ((t & 31) == 0) red[t >> 5] = s;
    __syncthreads();
    float tot = red[0]+red[1]+red[2]+red[3]+red[4]+red[5]+red[6]+red[7];
    const float mu = tot * (1.0f / C_);

    float d0 = v0 - mu, d1 = v1 - mu, d2 = v2 - mu;
    float q = d0*d0 + d1*d1 + d2*d2;
    #pragma unroll
    for (int o = 16; o; o >>= 1) q += __shfl_xor_sync(0xffffffffu, q, o);
    __syncthreads();
    if ((t & 31) == 0) red[t >> 5] = q;
    __syncthreads();
    float var = (red[0]+red[1]+red[2]+red[3]+red[4]+red[5]+red[6]+red[7]) * (1.0f / C_);
    const float rstd = rsqrtf(var + 1e-5f);

    __half* orow = out + (size_t)row * C_;
    orow[t]       = __float2half_rn(d0 * rstd * w[t]       + b[t]);
    orow[t + 256] = __float2half_rn(d1 * rstd * w[t + 256] + b[t + 256]);
    orow[t + 512] = __float2half_rn(d2 * rstd * w[t + 512] + b[t + 512]);
}

// ================= flash attention fp16 v2: cp.async pipeline ==============
// Inputs pre-formatted by QKV epilogue: Qh/Ql (split halves), K/V half.
// K non-trans ldmatrix; V row-major + ldmatrix.trans. 3-stage K/V ring.
#define ASTR 72
#define QH_B 0
#define QL_B (128*ASTR*2)             // 18432
#define ST_B (2*128*ASTR*2)           // 36864
#define KV_STAGE (64*ASTR*2*2)        // 18432 (K 9216 + V 9216)
#define ATT_SMEM (ST_B + 3*KV_STAGE)  // 92160 B

__global__ void __launch_bounds__(256, 2) attn_mma(const __half* __restrict__ qh,
                                                   const __half* __restrict__ ql,
                                                   const __half* __restrict__ kv,
                                                   __half* __restrict__ out)
{
    extern __shared__ char smc[];
    const uint32_t sbase = smem_u32(smc);

    const int qt = blockIdx.x;
    const int bh = blockIdx.y;
    const int h  = bh % H_;
    const int b  = bh / H_;
    const int tid = threadIdx.x;
    const int w = tid >> 5, lane = tid & 31;
    const int qr = lane >> 2, qc = lane & 3;
    const int mrow = w * 16;
    const size_t rowbase = (size_t)b * N_ + (size_t)qt * 128;

    const int l7 = lane & 7;
    const uint32_t aOff = (uint32_t)((mrow + l7 + ((lane >> 3) & 1) * 8) * ASTR * 2
                                     + ((lane >> 4) & 1) * 16);
    const uint32_t bOff = (uint32_t)((l7 + ((lane >> 4) & 1) * 8) * ASTR * 2
                                     + ((lane >> 3) & 1) * 16);
    // V trans fragment: rows = key (k), col groups select n (d) halves
    const uint32_t vOff = (uint32_t)((l7 + ((lane >> 3) & 1) * 8) * ASTR * 2
                                     + ((lane >> 4) & 1) * 16);

    auto load_kv = [&](int kt) {
        const uint32_t sK = sbase + (uint32_t)ST_B + (uint32_t)((kt % 3) * KV_STAGE);
        const uint32_t sV = sK + 64 * ASTR * 2;
        #pragma unroll
        for (int t = 0; t < 2; t++) {
            const int i = tid + t * 256;      // 512 chunks
            const int row = i >> 3, seg = i & 7;
            const __half* src = kv + ((size_t)b * N_ + kt * 64 + row) * (2 * C_) + h * D_ + seg * 8;
            cp16(sK + (uint32_t)(row * ASTR * 2 + seg * 16), src);
            cp16(sV + (uint32_t)(row * ASTR * 2 + seg * 16), src + C_);
        }
        asm volatile("cp.async.commit_group;" ::: "memory");
    };

    // group 0: Q (hi+lo) + KV tile 0
    #pragma unroll
    for (int t = 0; t < 4; t++) {
        const int i = tid + t * 256;          // 1024 chunks
        const int row = i >> 3, seg = i & 7;
        const size_t goff = (rowbase + row) * C_ + h * D_ + seg * 8;
        cp16(sbase + (uint32_t)QH_B + (uint32_t)(row * ASTR * 2 + seg * 16), qh + goff);
        cp16(sbase + (uint32_t)QL_B + (uint32_t)(row * ASTR * 2 + seg * 16), ql + goff);
    }
    load_kv(0);     // commits group 0 (Q + kv0)
    load_kv(1);     // group 1

    float m0 = -INFINITY, m1 = -INFINITY, l0s = 0.0f, l1s = 0.0f;
    float O[8][4];
    #pragma unroll
    for (int nt = 0; nt < 8; nt++)
        #pragma unroll
        for (int u = 0; u < 4; u++) O[nt][u] = 0.0f;

    for (int kt = 0; kt < 8; kt++) {
        if (kt == 7) asm volatile("cp.async.wait_group 0;" ::: "memory");
        else         asm volatile("cp.async.wait_group 1;" ::: "memory");
        __syncthreads();
        if (kt + 2 < 8) load_kv(kt + 2);

        const uint32_t sK = sbase + (uint32_t)ST_B + (uint32_t)((kt % 3) * KV_STAGE);
        const uint32_t sV = sK + 64 * ASTR * 2;

        // ---- S = (Qh+Ql) Kh^T ----
        float S[8][4];
        #pragma unroll
        for (int nt = 0; nt < 8; nt++)
            #pragma unroll
            for (int u = 0; u < 4; u++) S[nt][u] = 0.0f;

        #pragma unroll
        for (int kk = 0; kk < 4; kk++) {
            uint32_t ah[4], al[4];
            ldsm_x4(ah, sbase + (uint32_t)QH_B + aOff + (uint32_t)(kk * 32));
            ldsm_x4(al, sbase + (uint32_t)QL_B + aOff + (uint32_t)(kk * 32));
            #pragma unroll
            for (int np = 0; np < 4; np++) {
                uint32_t kh4[4];
                ldsm_x4(kh4, sK + bOff + (uint32_t)(np * 16 * ASTR * 2 + kk * 32));
                mma_f16(S[2*np],   ah, kh4);
                mma_f16(S[2*np],   al, kh4);
                mma_f16(S[2*np+1], ah, kh4 + 2);
                mma_f16(S[2*np+1], al, kh4 + 2);
            }
        }

        // ---- online softmax ----
        float mt0 = -INFINITY, mt1 = -INFINITY;
        #pragma unroll
        for (int nt = 0; nt < 8; nt++) {
            #pragma unroll
            for (int u = 0; u < 4; u++) S[nt][u] *= 0.125f;
            mt0 = fmaxf(mt0, fmaxf(S[nt][0], S[nt][1]));
            mt1 = fmaxf(mt1, fmaxf(S[nt][2], S[nt][3]));
        }
        mt0 = fmaxf(mt0, __shfl_xor_sync(0xffffffffu, mt0, 1));
        mt0 = fmaxf(mt0, __shfl_xor_sync(0xffffffffu, mt0, 2));
        mt1 = fmaxf(mt1, __shfl_xor_sync(0xffffffffu, mt1, 1));
        mt1 = fmaxf(mt1, __shfl_xor_sync(0xffffffffu, mt1, 2));
        const float mn0 = fmaxf(m0, mt0), mn1 = fmaxf(m1, mt1);
        const float a0 = __expf(m0 - mn0), a1 = __expf(m1 - mn1);
        float ls0 = 0.0f, ls1 = 0.0f;
        #pragma unroll
        for (int nt = 0; nt < 8; nt++) {
            S[nt][0] = __expf(S[nt][0] - mn0);
            S[nt][1] = __expf(S[nt][1] - mn0);
            S[nt][2] = __expf(S[nt][2] - mn1);
            S[nt][3] = __expf(S[nt][3] - mn1);
            ls0 += S[nt][0] + S[nt][1];
            ls1 += S[nt][2] + S[nt][3];
        }
        ls0 += __shfl_xor_sync(0xffffffffu, ls0, 1);
        ls0 += __shfl_xor_sync(0xffffffffu, ls0, 2);
        ls1 += __shfl_xor_sync(0xffffffffu, ls1, 1);
        ls1 += __shfl_xor_sync(0xffffffffu, ls1, 2);
        l0s = l0s * a0 + ls0;
        l1s = l1s * a1 + ls1;
        m0 = mn0; m1 = mn1;
        #pragma unroll
        for (int nt = 0; nt < 8; nt++) {
            O[nt][0] *= a0; O[nt][1] *= a0;
            O[nt][2] *= a1; O[nt][3] *= a1;
        }

        // ---- O += (Ph+Pl) Vh: V via ldmatrix.trans ----
        #pragma unroll
        for (int j = 0; j < 4; j++) {
            __half2 h0 = __floats2half2_rn(S[2*j][0],   S[2*j][1]);
            __half2 h1 = __floats2half2_rn(S[2*j][2],   S[2*j][3]);
            __half2 h2 = __floats2half2_rn(S[2*j+1][0], S[2*j+1][1]);
            __half2 h3 = __floats2half2_rn(S[2*j+1][2], S[2*j+1][3]);
            float2 f0 = __half22float2(h0), f1 = __half22float2(h1);
            float2 f2 = __half22float2(h2), f3 = __half22float2(h3);
            uint32_t ph[4] = { h2u(h0), h2u(h1), h2u(h2), h2u(h3) };
            uint32_t pl[4] = {
                h2u(__floats2half2_rn(S[2*j][0]   - f0.x, S[2*j][1]   - f0.y)),
                h2u(__floats2half2_rn(S[2*j][2]   - f1.x, S[2*j][3]   - f1.y)),
                h2u(__floats2half2_rn(S[2*j+1][0] - f2.x, S[2*j+1][1] - f2.y)),
                h2u(__floats2half2_rn(S[2*j+1][2] - f3.x, S[2*j+1][3] - f3.y))
            };
            #pragma unroll
            for (int np = 0; np < 4; np++) {
                uint32_t vt4[4];
                ldsm_x4t(vt4, sV + vOff + (uint32_t)(j * 16 * ASTR * 2 + np * 32));
                mma_f16(O[2*np],   ph, vt4);
                mma_f16(O[2*np],   pl, vt4);
                mma_f16(O[2*np+1], ph, vt4 + 2);
                mma_f16(O[2*np+1], pl, vt4 + 2);
            }
        }
    }

    const float inv0 = 1.0f / l0s, inv1 = 1.0f / l1s;
    #pragma unroll
    for (int nt = 0; nt < 8; nt++) {
        const int col = h * D_ + nt * 8 + 2 * qc;
        const size_t r0 = rowbase + mrow + qr;
        *(__half2*)(out + r0 * C_ + col) =
            __floats2half2_rn(O[nt][0] * inv0, O[nt][1] * inv0);
        *(__half2*)(out + (r0 + 8) * C_ + col) =
            __floats2half2_rn(O[nt][2] * inv1, O[nt][3] * inv1);
    }
}

// ---------------- host launcher -------------------------------------------
extern "C" void kernel_launch(void* const* d_in, const int* in_sizes, int n_in,
                              void* d_out, int out_size)
{
    (void)in_sizes; (void)n_in; (void)out_size;
    const float* x      = (const float*)d_in[0];
    const float* ln1_w  = (const float*)d_in[1];
    const float* ln1_b  = (const float*)d_in[2];
    const float* qkv_w  = (const float*)d_in[3];
    const float* proj_w = (const float*)d_in[4];
    const float* proj_b = (const float*)d_in[5];
    const float* ln2_w  = (const float*)d_in[6];
    const float* ln2_b  = (const float*)d_in[7];
    const float* fc1_w  = (const float*)d_in[8];
    const float* fc1_b  = (const float*)d_in[9];
    const float* fc2_w  = (const float*)d_in[10];
    const float* fc2_b  = (const float*)d_in[11];
    float* out = (float*)d_out;

    __half *h1, *qh, *ql, *kv, *attn, *ln2o, *fc1o, *rw;
    float *x2;
    cudaGetSymbolAddress((void**)&h1,   g_h1);
    cudaGetSymbolAddress((void**)&qh,   g_qh);
    cudaGetSymbolAddress((void**)&ql,   g_ql);
    cudaGetSymbolAddress((void**)&kv,   g_kv);
    cudaGetSymbolAddress((void**)&attn, g_attn);
    cudaGetSymbolAddress((void**)&x2,   g_x2);
    cudaGetSymbolAddress((void**)&ln2o, g_ln2);
    cudaGetSymbolAddress((void**)&fc1o, g_fc1);
    cudaGetSymbolAddress((void**)&rw,   g_rw);

    static bool attr_done = false;
    if (!attr_done) {
        cudaFuncSetAttribute(tc_gemm<0>, cudaFuncAttributeMaxDynamicSharedMemorySize, GSMEM);
        cudaFuncSetAttribute(tc_gemm<1>, cudaFuncAttributeMaxDynamicSharedMemorySize, GSMEM);
        cudaFuncSetAttribute(tc_gemm<2>, cudaFuncAttributeMaxDynamicSharedMemorySize, GSMEM);
        cudaFuncSetAttribute(tc_gemm<3>, cudaFuncAttributeMaxDynamicSharedMemorySize, GSMEM);
        cudaFuncSetAttribute(attn_mma,   cudaFuncAttributeMaxDynamicSharedMemorySize, ATT_SMEM);
        attr_done = true;
    }

    round_all_kernel<<<(RW_TOT/4 + 255)/256, 256>>>(qkv_w, proj_w, fc1_w, fc2_w, rw);

    ln_kernel<<<M_, 256>>>(x, ln1_w, ln1_b, h1);
    tc_gemm<0><<<dim3(3*C_/128, M_/128), 128, GSMEM>>>(h1, rw + RW_QKV, nullptr, nullptr, qh, ql, kv, M_, 3*C_, C_);
    attn_mma<<<dim3(4, B_*H_), 256, ATT_SMEM>>>(qh, ql, kv, attn);
    tc_gemm<1><<<dim3(C_/128, M_/128), 128, GSMEM>>>(attn, rw + RW_PROJ, proj_b, nullptr, x2, nullptr, nullptr, M_, C_, C_);
    ln_kernel<<<M_, 256>>>(x2, ln2_w, ln2_b, ln2o);
    tc_gemm<2><<<dim3(HID_/128, M_/128), 128, GSMEM>>>(ln2o, rw + RW_FC1, fc1_b, nullptr, fc1o, nullptr, nullptr, M_, HID_, C_);
    tc_gemm<3><<<dim3(C_/128, M_/128), 128, GSMEM>>>(fc1o, rw + RW_FC2, fc2_b, x2, out, nullptr, nullptr, M_, C_, HID_);
}

// round 16
// speedup vs baseline: 2.8556x; 1.0245x over previous
#include <cuda_runtime.h>
#include <cuda_fp16.h>
#include <math.h>
#include <stdint.h>

#define B_   32
#define N_   512
#define C_   768
#define H_   12
#define D_   64
#define HID_ 3072
#define M_   (B_*N_)   // 16384 rows

// ---------------- scratch (device globals; no allocation allowed) ----------
__device__ __half g_h1  [(size_t)M_ * C_];
__device__ __half g_qh  [(size_t)M_ * C_];
__device__ __half g_ql  [(size_t)M_ * C_];
__device__ __half g_kv  [(size_t)M_ * 2 * C_];
__device__ __half g_attn[(size_t)M_ * C_];
__device__ float  g_x2  [(size_t)M_ * C_];
__device__ __half g_ln2 [(size_t)M_ * C_];
__device__ __half g_fc1 [(size_t)M_ * HID_];
#define RW_QKV 0
#define RW_PROJ (3*C_*C_)
#define RW_FC1  (RW_PROJ + C_*C_)
#define RW_FC2  (RW_FC1 + HID_*C_)
#define RW_TOT  (RW_FC2 + C_*HID_)
__device__ __half g_rw[(size_t)RW_TOT];

// ================= small helpers ===========================================
__device__ __forceinline__ void cp16(uint32_t saddr, const void* g) {
    asm volatile("cp.async.cg.shared.global [%0], [%1], 16;" :: "r"(saddr), "l"(g) : "memory");
}
__device__ __forceinline__ uint32_t smem_u32(const void* p) {
    uint32_t a;
    asm("{ .reg .u64 t; cvta.to.shared.u64 t, %1; cvt.u32.u64 %0, t; }" : "=r"(a) : "l"(p));
    return a;
}
__device__ __forceinline__ uint32_t h2u(__half2 h) { return *(uint32_t*)&h; }
__device__ __forceinline__ void mma_f16(float* c, const uint32_t* a, const uint32_t* b) {
    asm volatile("mma.sync.aligned.m16n8k16.row.col.f32.f16.f16.f32 "
                 "{%0,%1,%2,%3}, {%4,%5,%6,%7}, {%8,%9}, {%0,%1,%2,%3};"
                 : "+f"(c[0]), "+f"(c[1]), "+f"(c[2]), "+f"(c[3])
                 : "r"(a[0]), "r"(a[1]), "r"(a[2]), "r"(a[3]), "r"(b[0]), "r"(b[1]));
}
__device__ __forceinline__ void ldsm_x4(uint32_t* r, uint32_t addr) {
    asm volatile("ldmatrix.sync.aligned.m8n8.x4.shared.b16 {%0,%1,%2,%3}, [%4];"
                 : "=r"(r[0]), "=r"(r[1]), "=r"(r[2]), "=r"(r[3]) : "r"(addr));
}
__device__ __forceinline__ void ldsm_x4t(uint32_t* r, uint32_t addr) {
    asm volatile("ldmatrix.sync.aligned.m8n8.x4.trans.shared.b16 {%0,%1,%2,%3}, [%4];"
                 : "=r"(r[0]), "=r"(r[1]), "=r"(r[2]), "=r"(r[3]) : "r"(addr));
}

// ================= weight fp16 pre-round (single kernel) ===================
__global__ void __launch_bounds__(256) round_all_kernel(const float* __restrict__ w0,
                                                        const float* __restrict__ w1,
                                                        const float* __restrict__ w2,
                                                        const float* __restrict__ w3,
                                                        __half* __restrict__ out)
{
    const size_t i = ((size_t)blockIdx.x * 256 + threadIdx.x) * 4;
    if (i >= (size_t)RW_TOT) return;
    const float* src;
    size_t off;
    if (i < (size_t)RW_PROJ)      { src = w0; off = i; }
    else if (i < (size_t)RW_FC1)  { src = w1; off = i - RW_PROJ; }
    else if (i < (size_t)RW_FC2)  { src = w2; off = i - RW_FC1; }
    else                          { src = w3; off = i - RW_FC2; }
    float4 v = *(const float4*)(src + off);
    *(__half2*)(out + i)     = __floats2half2_rn(v.x, v.y);
    *(__half2*)(out + i + 2) = __floats2half2_rn(v.z, v.w);
}

// ================= fp16 mma.sync GEMM ======================================
#define BKH 64
#define ROWB 144
#define AT_BYTES (128 * ROWB)
#define STAGE_B  (2 * AT_BYTES)
#define GSMEM    (3 * STAGE_B)

template <int MODE>
__global__ void __launch_bounds__(128) tc_gemm(const __half* __restrict__ A,
                                               const __half* __restrict__ W,
                                               const float* __restrict__ bias,
                                               const float* __restrict__ res,
                                               void* __restrict__ out0,
                                               void* __restrict__ out1,
                                               void* __restrict__ out2,
                                               int M, int Nn, int K)
{
    extern __shared__ char smem[];
    const uint32_t sbase = smem_u32(smem);
    const int tid = threadIdx.x;
    const int bm = blockIdx.y, bn = blockIdx.x;

    const __half* Ab = A + (size_t)bm * 128 * K;
    const __half* Wb = W + (size_t)bn * 128 * K;
    const int nk = K / BKH;

    auto load_stage = [&](int slot, int k0) {
        const uint32_t sA = sbase + slot * STAGE_B;
        const uint32_t sB = sA + AT_BYTES;
        #pragma unroll
        for (int t = 0; t < 8; t++) {
            const int c = tid + 128 * t;
            const int row = c >> 3;
            const int seg = c & 7;
            const uint32_t off = (uint32_t)(row * ROWB + seg * 16);
            cp16(sA + off, Ab + (size_t)row * K + k0 + seg * 8);
            cp16(sB + off, Wb + (size_t)row * K + k0 + seg * 8);
        }
        asm volatile("cp.async.commit_group;" ::: "memory");
    };

    load_stage(0, 0);
    load_stage(1, BKH);

    const int wid = tid >> 5, lane = tid & 31;
    const int wm = (wid >> 1) * 64;
    const int wn = (wid & 1) * 64;
    const int qr = lane >> 2, qc = lane & 3;

    const int l7 = lane & 7;
    const uint32_t aOff = (uint32_t)((wm + l7 + ((lane >> 3) & 1) * 8) * ROWB
                                     + ((lane >> 4) & 1) * 16);
    const uint32_t bOff = (uint32_t)((wn + l7 + ((lane >> 4) & 1) * 8) * ROWB
                                     + ((lane >> 3) & 1) * 16);

    float acc[4][8][4];
    #pragma unroll
    for (int mi = 0; mi < 4; mi++)
        #pragma unroll
        for (int ni = 0; ni < 8; ni++)
            #pragma unroll
            for (int u = 0; u < 4; u++) acc[mi][ni][u] = 0.0f;

    int slot = 0, slot2 = 2;
    for (int i = 0; i < nk; i++) {
        if (i == nk - 1) asm volatile("cp.async.wait_group 0;" ::: "memory");
        else             asm volatile("cp.async.wait_group 1;" ::: "memory");
        __syncthreads();
        if (i + 2 < nk) load_stage(slot2, (i + 2) * BKH);

        const uint32_t sA = sbase + slot * STAGE_B;
        const uint32_t sB = sA + AT_BYTES;
        #pragma unroll
        for (int kc = 0; kc < 4; kc++) {
            uint32_t af[4][4], bf[4][4];
            #pragma unroll
            for (int mi = 0; mi < 4; mi++)
                ldsm_x4(af[mi], sA + aOff + (uint32_t)(mi * 16 * ROWB) + (uint32_t)(kc * 32));
            #pragma unroll
            for (int np = 0; np < 4; np++)
                ldsm_x4(bf[np], sB + bOff + (uint32_t)(np * 16 * ROWB) + (uint32_t)(kc * 32));
            #pragma unroll
            for (int mi = 0; mi < 4; mi++)
                #pragma unroll
                for (int ni = 0; ni < 8; ni++)
                    mma_f16(acc[mi][ni], af[mi], &bf[ni >> 1][(ni & 1) * 2]);
        }
        slot = (slot + 1 == 3) ? 0 : slot + 1;
        slot2 = (slot2 + 1 == 3) ? 0 : slot2 + 1;
    }

    #pragma unroll
    for (int mi = 0; mi < 4; mi++) {
        #pragma unroll
        for (int ni = 0; ni < 8; ni++) {
            const int col = bn * 128 + wn + ni * 8 + 2 * qc;
            #pragma unroll
            for (int half_ = 0; half_ < 2; half_++) {
                const size_t row = (size_t)bm * 128 + wm + mi * 16 + qr + half_ * 8;
                float v0 = acc[mi][ni][half_ * 2 + 0];
                float v1 = acc[mi][ni][half_ * 2 + 1];
                if (MODE == 0) {
                    __half2 hv = __floats2half2_rn(v0, v1);
                    if (bn < 6) {
                        float2 f = __half22float2(hv);
                        __half2 lv = __floats2half2_rn(v0 - f.x, v1 - f.y);
                        *(__half2*)((__half*)out0 + row * C_ + col) = hv;
                        *(__half2*)((__half*)out1 + row * C_ + col) = lv;
                    } else {
                        *(__half2*)((__half*)out2 + row * (2 * C_) + (col - C_)) = hv;
                    }
                } else if (MODE == 1) {
                    v0 = 2.0f * (v0 + bias[col]);
                    v1 = 2.0f * (v1 + bias[col + 1]);
                    *(float2*)((float*)out0 + row * Nn + col) = make_float2(v0, v1);
                } else if (MODE == 2) {
                    v0 += bias[col];
                    v1 += bias[col + 1];
                    v0 = 0.5f * v0 * (1.0f + erff(v0 * 0.70710678118654752f));
                    v1 = 0.5f * v1 * (1.0f + erff(v1 * 0.70710678118654752f));
                    *(__half2*)((__half*)out0 + row * Nn + col) = __floats2half2_rn(v0, v1);
                } else {
                    const float* rr = res + row * Nn + col;
                    v0 += bias[col] + rr[0];
                    v1 += bias[col + 1] + rr[1];
                    *(float2*)((float*)out0 + row * Nn + col) = make_float2(v0, v1);
                }
            }
        }
    }
}

// ---------------- LayerNorm: one warp per row, shfl-only, fp16 out ---------
__global__ void __launch_bounds__(256) ln_kernel(const float* __restrict__ x,
                                                 const float* __restrict__ w,
                                                 const float* __restrict__ b,
                                                 __half* __restrict__ out)
{
    const int row = blockIdx.x * 8 + (threadIdx.x >> 5);
    const int lane = threadIdx.x & 31;
    const float* xr = x + (size_t)row * C_;

    float4 v[6];
    float s = 0.0f;
    #pragma unroll
    for (int i = 0; i < 6; i++) {
        v[i] = *(const float4*)(xr + i * 128 + lane * 4);
        s += (v[i].x + v[i].y) + (v[i].z + v[i].w);
    }
    #pragma unroll
    for (int o = 16; o; o >>= 1) s += __shfl_xor_sync(0xffffffffu, s, o);
    const float mu = s * (1.0f / C_);

    float q = 0.0f;
    #pragma unroll
    for (int i = 0; i < 6; i++) {
        v[i].x -= mu; v[i].y -= mu; v[i].z -= mu; v[i].w -= mu;
        q += (v[i].x * v[i].x + v[i].y * v[i].y) + (v[i].z * v[i].z + v[i].w * v[i].w);
    }
    #pragma unroll
    for (int o = 16; o; o >>= 1) q += __shfl_xor_sync(0xffffffffu, q, o);
    const float rstd = rsqrtf(q * (1.0f / C_) + 1e-5f);

    __half* orow = out + (size_t)row * C_;
    #pragma unroll
    for (int i = 0; i < 6; i++) {
        const int col = i * 128 + lane * 4;
        float4 wv = *(const float4*)(w + col);
        float4 bv = *(const float4*)(b + col);
        float o0 = v[i].x * rstd * wv.x + bv.x;
        float o1 = v[i].y * rstd * wv.y + bv.y;
        float o2 = v[i].z * rstd * wv.z + bv.z;
        float o3 = v[i].w * rstd * wv.w + bv.w;
        *(__half2*)(orow + col)     = __floats2half2_rn(o0, o1);
        *(__half2*)(orow + col + 2) = __floats2half2_rn(o2, o3);
    }
}

// ================= flash attention fp16 v2: cp.async pipeline ==============
#define ASTR 72
#define QH_B 0
#define QL_B (128*ASTR*2)
#define ST_B (2*128*ASTR*2)
#define KV_STAGE (64*ASTR*2*2)
#define ATT_SMEM (ST_B + 3*KV_STAGE)

__global__ void __launch_bounds__(256, 2) attn_mma(const __half* __restrict__ qh,
                                                   const __half* __restrict__ ql,
                                                   const __half* __restrict__ kv,
                                                   __half* __restrict__ out)
{
    extern __shared__ char smc[];
    const uint32_t sbase = smem_u32(smc);

    const int qt = blockIdx.x;
    const int bh = blockIdx.y;
    const int h  = bh % H_;
    const int b  = bh / H_;
    const int tid = threadIdx.x;
    const int w = tid >> 5, lane = tid & 31;
    const int qr = lane >> 2, qc = lane & 3;
    const int mrow = w * 16;
    const size_t rowbase = (size_t)b * N_ + (size_t)qt * 128;

    const int l7 = lane & 7;
    const uint32_t aOff = (uint32_t)((mrow + l7 + ((lane >> 3) & 1) * 8) * ASTR * 2
                                     + ((lane >> 4) & 1) * 16);
    const uint32_t bOff = (uint32_t)((l7 + ((lane >> 4) & 1) * 8) * ASTR * 2
                                     + ((lane >> 3) & 1) * 16);
    const uint32_t vOff = (uint32_t)((l7 + ((lane >> 3) & 1) * 8) * ASTR * 2
                                     + ((lane >> 4) & 1) * 16);

    auto load_kv = [&](int kt) {
        const uint32_t sK = sbase + (uint32_t)ST_B + (uint32_t)((kt % 3) * KV_STAGE);
        const uint32_t sV = sK + 64 * ASTR * 2;
        #pragma unroll
        for (int t = 0; t < 2; t++) {
            const int i = tid + t * 256;
            const int row = i >> 3, seg = i & 7;
            const __half* src = kv + ((size_t)b * N_ + kt * 64 + row) * (2 * C_) + h * D_ + seg * 8;
            cp16(sK + (uint32_t)(row * ASTR * 2 + seg * 16), src);
            cp16(sV + (uint32_t)(row * ASTR * 2 + seg * 16), src + C_);
        }
        asm volatile("cp.async.commit_group;" ::: "memory");
    };

    #pragma unroll
    for (int t = 0; t < 4; t++) {
        const int i = tid + t * 256;
        const int row = i >> 3, seg = i & 7;
        const size_t goff = (rowbase + row) * C_ + h * D_ + seg * 8;
        cp16(sbase + (uint32_t)QH_B + (uint32_t)(row * ASTR * 2 + seg * 16), qh + goff);
        cp16(sbase + (uint32_t)QL_B + (uint32_t)(row * ASTR * 2 + seg * 16), ql + goff);
    }
    load_kv(0);
    load_kv(1);

    float m0 = -INFINITY, m1 = -INFINITY, l0s = 0.0f, l1s = 0.0f;
    float O[8][4];
    #pragma unroll
    for (int nt = 0; nt < 8; nt++)
        #pragma unroll
        for (int u = 0; u < 4; u++) O[nt][u] = 0.0f;

    for (int kt = 0; kt < 8; kt++) {
        if (kt == 7) asm volatile("cp.async.wait_group 0;" ::: "memory");
        else         asm volatile("cp.async.wait_group 1;" ::: "memory");
        __syncthreads();
        if (kt + 2 < 8) load_kv(kt + 2);

        const uint32_t sK = sbase + (uint32_t)ST_B + (uint32_t)((kt % 3) * KV_STAGE);
        const uint32_t sV = sK + 64 * ASTR * 2;

        float S[8][4];
        #pragma unroll
        for (int nt = 0; nt < 8; nt++)
            #pragma unroll
            for (int u = 0; u < 4; u++) S[nt][u] = 0.0f;

        #pragma unroll
        for (int kk = 0; kk < 4; kk++) {
            uint32_t ah[4], al[4];
            ldsm_x4(ah, sbase + (uint32_t)QH_B + aOff + (uint32_t)(kk * 32));
            ldsm_x4(al, sbase + (uint32_t)QL_B + aOff + (uint32_t)(kk * 32));
            #pragma unroll
            for (int np = 0; np < 4; np++) {
                uint32_t kh4[4];
                ldsm_x4(kh4, sK + bOff + (uint32_t)(np * 16 * ASTR * 2 + kk * 32));
                mma_f16(S[2*np],   ah, kh4);
                mma_f16(S[2*np],   al, kh4);
                mma_f16(S[2*np+1], ah, kh4 + 2);
                mma_f16(S[2*np+1], al, kh4 + 2);
            }
        }

        float mt0 = -INFINITY, mt1 = -INFINITY;
        #pragma unroll
        for (int nt = 0; nt < 8; nt++) {
            #pragma unroll
            for (int u = 0; u < 4; u++) S[nt][u] *= 0.125f;
            mt0 = fmaxf(mt0, fmaxf(S[nt][0], S[nt][1]));
            mt1 = fmaxf(mt1, fmaxf(S[nt][2], S[nt][3]));
        }
        mt0 = fmaxf(mt0, __shfl_xor_sync(0xffffffffu, mt0, 1));
        mt0 = fmaxf(mt0, __shfl_xor_sync(0xffffffffu, mt0, 2));
        mt1 = fmaxf(mt1, __shfl_xor_sync(0xffffffffu, mt1, 1));
        mt1 = fmaxf(mt1, __shfl_xor_sync(0xffffffffu, mt1, 2));
        const float mn0 = fmaxf(m0, mt0), mn1 = fmaxf(m1, mt1);
        const float a0 = __expf(m0 - mn0), a1 = __expf(m1 - mn1);
        float ls0 = 0.0f, ls1 = 0.0f;
        #pragma unroll
        for (int nt = 0; nt < 8; nt++) {
            S[nt][0] = __expf(S[nt][0] - mn0);
            S[nt][1] = __expf(S[nt][1] - mn0);
            S[nt][2] = __expf(S[nt][2] - mn1);
            S[nt][3] = __expf(S[nt][3] - mn1);
            ls0 += S[nt][0] + S[nt][1];
            ls1 += S[nt][2] + S[nt][3];
        }
        ls0 += __shfl_xor_sync(0xffffffffu, ls0, 1);
        ls0 += __shfl_xor_sync(0xffffffffu, ls0, 2);
        ls1 += __shfl_xor_sync(0xffffffffu, ls1, 1);
        ls1 += __shfl_xor_sync(0xffffffffu, ls1, 2);
        l0s = l0s * a0 + ls0;
        l1s = l1s * a1 + ls1;
        m0 = mn0; m1 = mn1;
        #pragma unroll
        for (int nt = 0; nt < 8; nt++) {
            O[nt][0] *= a0; O[nt][1] *= a0;
            O[nt][2] *= a1; O[nt][3] *= a1;
        }

        #pragma unroll
        for (int j = 0; j < 4; j++) {
            __half2 h0 = __floats2half2_rn(S[2*j][0],   S[2*j][1]);
            __half2 h1 = __floats2half2_rn(S[2*j][2],   S[2*j][3]);
            __half2 h2 = __floats2half2_rn(S[2*j+1][0], S[2*j+1][1]);
            __half2 h3 = __floats2half2_rn(S[2*j+1][2], S[2*j+1][3]);
            float2 f0 = __half22float2(h0), f1 = __half22float2(h1);
            float2 f2 = __half22float2(h2), f3 = __half22float2(h3);
            uint32_t ph[4] = { h2u(h0), h2u(h1), h2u(h2), h2u(h3) };
            uint32_t pl[4] = {
                h2u(__floats2half2_rn(S[2*j][0]   - f0.x, S[2*j][1]   - f0.y)),
                h2u(__floats2half2_rn(S[2*j][2]   - f1.x, S[2*j][3]   - f1.y)),
                h2u(__floats2half2_rn(S[2*j+1][0] - f2.x, S[2*j+1][1] - f2.y)),
                h2u(__floats2half2_rn(S[2*j+1][2] - f3.x, S[2*j+1][3] - f3.y))
            };
            #pragma unroll
            for (int np = 0; np < 4; np++) {
                uint32_t vt4[4];
                ldsm_x4t(vt4, sV + vOff + (uint32_t)(j * 16 * ASTR * 2 + np * 32));
                mma_f16(O[2*np],   ph, vt4);
                mma_f16(O[2*np],   pl, vt4);
                mma_f16(O[2*np+1], ph, vt4 + 2);
                mma_f16(O[2*np+1], pl, vt4 + 2);
            }
        }
    }

    const float inv0 = 1.0f / l0s, inv1 = 1.0f / l1s;
    #pragma unroll
    for (int nt = 0; nt < 8; nt++) {
        const int col = h * D_ + nt * 8 + 2 * qc;
        const size_t r0 = rowbase + mrow + qr;
        *(__half2*)(out + r0 * C_ + col) =
            __floats2half2_rn(O[nt][0] * inv0, O[nt][1] * inv0);
        *(__half2*)(out + (r0 + 8) * C_ + col) =
            __floats2half2_rn(O[nt][2] * inv1, O[nt][3] * inv1);
    }
}

// ---------------- host launcher -------------------------------------------
extern "C" void kernel_launch(void* const* d_in, const int* in_sizes, int n_in,
                              void* d_out, int out_size)
{
    (void)in_sizes; (void)n_in; (void)out_size;
    const float* x      = (const float*)d_in[0];
    const float* ln1_w  = (const float*)d_in[1];
    const float* ln1_b  = (const float*)d_in[2];
    const float* qkv_w  = (const float*)d_in[3];
    const float* proj_w = (const float*)d_in[4];
    const float* proj_b = (const float*)d_in[5];
    const float* ln2_w  = (const float*)d_in[6];
    const float* ln2_b  = (const float*)d_in[7];
    const float* fc1_w  = (const float*)d_in[8];
    const float* fc1_b  = (const float*)d_in[9];
    const float* fc2_w  = (const float*)d_in[10];
    const float* fc2_b  = (const float*)d_in[11];
    float* out = (float*)d_out;

    __half *h1, *qh, *ql, *kv, *attn, *ln2o, *fc1o, *rw;
    float *x2;
    cudaGetSymbolAddress((void**)&h1,   g_h1);
    cudaGetSymbolAddress((void**)&qh,   g_qh);
    cudaGetSymbolAddress((void**)&ql,   g_ql);
    cudaGetSymbolAddress((void**)&kv,   g_kv);
    cudaGetSymbolAddress((void**)&attn, g_attn);
    cudaGetSymbolAddress((void**)&x2,   g_x2);
    cudaGetSymbolAddress((void**)&ln2o, g_ln2);
    cudaGetSymbolAddress((void**)&fc1o, g_fc1);
    cudaGetSymbolAddress((void**)&rw,   g_rw);

    static bool attr_done = false;
    if (!attr_done) {
        cudaFuncSetAttribute(tc_gemm<0>, cudaFuncAttributeMaxDynamicSharedMemorySize, GSMEM);
        cudaFuncSetAttribute(tc_gemm<1>, cudaFuncAttributeMaxDynamicSharedMemorySize, GSMEM);
        cudaFuncSetAttribute(tc_gemm<2>, cudaFuncAttributeMaxDynamicSharedMemorySize, GSMEM);
        cudaFuncSetAttribute(tc_gemm<3>, cudaFuncAttributeMaxDynamicSharedMemorySize, GSMEM);
        cudaFuncSetAttribute(attn_mma,   cudaFuncAttributeMaxDynamicSharedMemorySize, ATT_SMEM);
        attr_done = true;
    }

    round_all_kernel<<<(RW_TOT/4 + 255)/256, 256>>>(qkv_w, proj_w, fc1_w, fc2_w, rw);

    ln_kernel<<<M_/8, 256>>>(x, ln1_w, ln1_b, h1);
    tc_gemm<0><<<dim3(3*C_/128, M_/128), 128, GSMEM>>>(h1, rw + RW_QKV, nullptr, nullptr, qh, ql, kv, M_, 3*C_, C_);
    attn_mma<<<dim3(4, B_*H_), 256, ATT_SMEM>>>(qh, ql, kv, attn);
    tc_gemm<1><<<dim3(C_/128, M_/128), 128, GSMEM>>>(attn, rw + RW_PROJ, proj_b, nullptr, x2, nullptr, nullptr, M_, C_, C_);
    ln_kernel<<<M_/8, 256>>>(x2, ln2_w, ln2_b, ln2o);
    tc_gemm<2><<<dim3(HID_/128, M_/128), 128, GSMEM>>>(ln2o, rw + RW_FC1, fc1_b, nullptr, fc1o, nullptr, nullptr, M_, HID_, C_);
    tc_gemm<3><<<dim3(C_/128, M_/128), 128, GSMEM>>>(fc1o, rw + RW_FC2, fc2_b, x2, out, nullptr, nullptr, M_, C_, HID_);
}